// round 6
// baseline (speedup 1.0000x reference)
#include <cuda_runtime.h>
#include <math.h>
#include <stdint.h>

#define BATCH 8
#define NTOK  2048
#define FDIM  64
#define ALPHA 0.2f

// ---------------- scratch (__device__ globals; no allocs allowed) ----------
__device__ __align__(16) float g_Wh[BATCH * NTOK * FDIM];   // [b][j][o], tf32-rounded
__device__ __align__(16) float4 g_suv[BATCH * NTOK];        // {sd, e^sd, e^(a*sd), 0}
__device__ float g_ssrc[BATCH * NTOK];
__device__ float g_maxs[BATCH];
// partials: [jsplit][b*2048+row][68]  (64 numer + 4 z-shares)
__device__ __align__(16) float g_part[2 * BATCH * NTOK * 68];

__device__ __forceinline__ float eluf(float x) { return x > 0.f ? x : expm1f(x); }

__device__ __forceinline__ uint32_t cvt_tf32(float x) {
    uint32_t r;
    asm("cvt.rna.tf32.f32 %0, %1;" : "=r"(r) : "f"(x));
    return r;
}

__device__ __forceinline__ void mma_tf32(float* d, uint32_t a0, uint32_t a1,
                                         uint32_t a2, uint32_t a3,
                                         uint32_t b0, uint32_t b1) {
    asm volatile(
        "mma.sync.aligned.m16n8k8.row.col.f32.tf32.tf32.f32 "
        "{%0,%1,%2,%3}, {%4,%5,%6,%7}, {%8,%9}, {%0,%1,%2,%3};"
        : "+f"(d[0]), "+f"(d[1]), "+f"(d[2]), "+f"(d[3])
        : "r"(a0), "r"(a1), "r"(a2), "r"(a3), "r"(b0), "r"(b1));
}

// ---------------------------------------------------------------------------
// Kernel 1: Wh = h @ W (tf32-rounded store), scores, packed suv.
//   256 thr = 2 k-halves x (16 row-groups x 8 col-octets); 4 rows/thread,
//   32 FMA chains, k-depth 32; halves combined via smem (stride-33 red).
// ---------------------------------------------------------------------------
__global__ void __launch_bounds__(256) k1_proj(const float* __restrict__ h,
                                               const float* __restrict__ W,
                                               const float* __restrict__ a) {
    __shared__ float S[8384];        // [W 4096][a 128][h 64*65=4160]; red overlays W+a
    float* W_s = S;
    float* a_s = S + 4096;
    float* h_s = S + 4224;

    int tid = threadIdx.x;
    int row0 = blockIdx.x * 64;
    for (int i = tid; i < 4096; i += 256) W_s[i] = W[i];
    if (tid < 128) a_s[tid] = a[tid];
    for (int i = tid; i < 4096; i += 256) h_s[(i >> 6) * 65 + (i & 63)] = h[row0 * 64 + i];
    __syncthreads();

    int kh = tid >> 7;               // k-half
    int sub = tid & 127;
    int g = sub >> 3, e = sub & 7;   // rows 4g..4g+3, cols e*4 & 32+e*4

    float acc[4][8];
#pragma unroll
    for (int rr = 0; rr < 4; rr++)
#pragma unroll
        for (int i = 0; i < 8; i++) acc[rr][i] = 0.f;

    int k0 = kh * 32;
#pragma unroll
    for (int kk = 0; kk < 32; kk++) {
        int k = k0 + kk;
        float4 w0 = *(const float4*)&W_s[k * 64 + e * 4];
        float4 w1 = *(const float4*)&W_s[k * 64 + 32 + e * 4];
#pragma unroll
        for (int rr = 0; rr < 4; rr++) {
            float hv = h_s[(g * 4 + rr) * 65 + k];
            acc[rr][0] = fmaf(hv, w0.x, acc[rr][0]);
            acc[rr][1] = fmaf(hv, w0.y, acc[rr][1]);
            acc[rr][2] = fmaf(hv, w0.z, acc[rr][2]);
            acc[rr][3] = fmaf(hv, w0.w, acc[rr][3]);
            acc[rr][4] = fmaf(hv, w1.x, acc[rr][4]);
            acc[rr][5] = fmaf(hv, w1.y, acc[rr][5]);
            acc[rr][6] = fmaf(hv, w1.z, acc[rr][6]);
            acc[rr][7] = fmaf(hv, w1.w, acc[rr][7]);
        }
    }

    // save needed a-values before red buffer overlays W_s/a_s
    float av0[4], av1[4], av2[4], av3[4];
#pragma unroll
    for (int i = 0; i < 4; i++) {
        av0[i] = a_s[e * 4 + i];
        av1[i] = a_s[32 + e * 4 + i];
        av2[i] = a_s[64 + e * 4 + i];
        av3[i] = a_s[96 + e * 4 + i];
    }
    __syncthreads();

    float* red = S;                  // 128 slots x stride 33 = 4224 floats
    if (kh == 1) {
#pragma unroll
        for (int rr = 0; rr < 4; rr++)
#pragma unroll
            for (int i = 0; i < 8; i++) red[sub * 33 + rr * 8 + i] = acc[rr][i];
    }
    __syncthreads();
    if (kh == 0) {
#pragma unroll
        for (int rr = 0; rr < 4; rr++)
#pragma unroll
            for (int i = 0; i < 8; i++) acc[rr][i] += red[sub * 33 + rr * 8 + i];

#pragma unroll
        for (int rr = 0; rr < 4; rr++) {
            int row = row0 + g * 4 + rr;
            float4 s0, s1;
            s0.x = __uint_as_float(cvt_tf32(acc[rr][0]));
            s0.y = __uint_as_float(cvt_tf32(acc[rr][1]));
            s0.z = __uint_as_float(cvt_tf32(acc[rr][2]));
            s0.w = __uint_as_float(cvt_tf32(acc[rr][3]));
            s1.x = __uint_as_float(cvt_tf32(acc[rr][4]));
            s1.y = __uint_as_float(cvt_tf32(acc[rr][5]));
            s1.z = __uint_as_float(cvt_tf32(acc[rr][6]));
            s1.w = __uint_as_float(cvt_tf32(acc[rr][7]));
            *(float4*)&g_Wh[(size_t)row * 64 + e * 4] = s0;
            *(float4*)&g_Wh[(size_t)row * 64 + 32 + e * 4] = s1;

            float ps = 0.f, pd = 0.f;
#pragma unroll
            for (int i = 0; i < 4; i++) {
                ps = fmaf(acc[rr][i], av0[i], ps);
                ps = fmaf(acc[rr][i + 4], av1[i], ps);
                pd = fmaf(acc[rr][i], av2[i], pd);
                pd = fmaf(acc[rr][i + 4], av3[i], pd);
            }
#pragma unroll
            for (int o = 1; o < 8; o <<= 1) {
                ps += __shfl_xor_sync(0xffffffffu, ps, o);
                pd += __shfl_xor_sync(0xffffffffu, pd, o);
            }
            if (e == 0) {
                g_ssrc[row] = ps;
                g_suv[row] = make_float4(pd, expf(pd), expf(ALPHA * pd), 0.f);
            }
        }
    }
}

// ---------------------------------------------------------------------------
// Kernel 2: per-batch max of s_dst.  Single block, warp per batch.
// ---------------------------------------------------------------------------
__global__ void __launch_bounds__(256) k2_max() {
    int w = threadIdx.x >> 5, lane = threadIdx.x & 31;
    float m = -1e30f;
    for (int j = lane; j < NTOK; j += 32) m = fmaxf(m, g_suv[w * NTOK + j].x);
#pragma unroll
    for (int o = 16; o > 0; o >>= 1)
        m = fmaxf(m, __shfl_xor_sync(0xffffffffu, m, o));
    if (lane == 0) g_maxs[w] = m;
}

// ---------------------------------------------------------------------------
// Kernel 3: attention partials, mma.sync tf32, double-buffered B tiles.
//   grid (32 i-tiles, 8 b, 2 j-halves); 256 thr = 2 m-warps x 4 j-split.
//   CTA: 64 i-rows x 1024 j (8 tiles of 128).  suv via __ldg (no smem).
//   Partial numerators + z-shares -> g_part; k4 combines.
// ---------------------------------------------------------------------------
#define TBYTES     (128 * 72 * 4)
#define SMEM3_TOTAL (2 * TBYTES)

__global__ void __launch_bounds__(256, 1) k3_attn() {
    extern __shared__ char smem[];
    float* Tb[2] = { (float*)smem, (float*)(smem + TBYTES) };

    int tid = threadIdx.x;
    int lane = tid & 31;
    int wid = tid >> 5;
    int mw = wid & 1, js = wid >> 1;
    int b = blockIdx.y;
    int i0 = blockIdx.x * 64;
    int jsp = blockIdx.z;
    int jbase = jsp * 1024;

    int q = lane >> 2, c4 = lane & 3;
    int rbase = i0 + mw * 32 + q;
    float M = g_maxs[b];
    float ssr[4], Ai[4], Bi[4];
#pragma unroll
    for (int rr = 0; rr < 4; rr++) {
        float s = g_ssrc[b * NTOK + rbase + rr * 8];
        float t = s + M;
        float m = t > 0.f ? t : ALPHA * t;
        ssr[rr] = s;
        Ai[rr] = expf(s - m);
        Bi[rr] = expf(ALPHA * s - m);
    }

    float acc[2][8][4];
    float z[4] = {0.f, 0.f, 0.f, 0.f};
#pragma unroll
    for (int mt = 0; mt < 2; mt++)
#pragma unroll
        for (int n = 0; n < 8; n++)
#pragma unroll
            for (int i = 0; i < 4; i++) acc[mt][n][i] = 0.f;

    const float4* WhG4 = (const float4*)(g_Wh + (size_t)b * NTOK * 64);
    const float4* suvg = (const float4*)(g_suv + b * NTOK);

    // stage tile 0 (Wh already tf32-rounded: raw copy)
#pragma unroll
    for (int it = 0; it < 8; it++) {
        int idx = tid + it * 256;
        int j = idx >> 4, o4 = idx & 15;
        float4 v = WhG4[(size_t)(jbase + j) * 16 + o4];
        *(float4*)&Tb[0][j * 72 + o4 * 4] = v;
    }
    __syncthreads();

    for (int t = 0; t < 8; t++) {
        const float* cur = Tb[t & 1];
        float* nxt = Tb[(t + 1) & 1];
        float4 pf[8];
        if (t < 7) {
#pragma unroll
            for (int it = 0; it < 8; it++) {
                int idx = tid + it * 256;
                pf[it] = WhG4[(size_t)(jbase + (t + 1) * 128 + (idx >> 4)) * 16 + (idx & 15)];
            }
        }

#pragma unroll
        for (int cc = 0; cc < 4; cc++) {
            int c = js * 4 + cc;
            int jb = jbase + t * 128 + c * 8;
            float4 s0 = __ldg(&suvg[jb + c4]);
            float4 s1 = __ldg(&suvg[jb + 4 + c4]);
            uint32_t af[2][4];
#pragma unroll
            for (int mt = 0; mt < 2; mt++) {
                int r0 = mt * 2, r1 = mt * 2 + 1;
                float p0 = (ssr[r0] + s0.x > 0.f) ? Ai[r0] * s0.y : Bi[r0] * s0.z;
                float p1 = (ssr[r1] + s0.x > 0.f) ? Ai[r1] * s0.y : Bi[r1] * s0.z;
                float p2 = (ssr[r0] + s1.x > 0.f) ? Ai[r0] * s1.y : Bi[r0] * s1.z;
                float p3 = (ssr[r1] + s1.x > 0.f) ? Ai[r1] * s1.y : Bi[r1] * s1.z;
                z[r0] += p0 + p2;
                z[r1] += p1 + p3;
                af[mt][0] = cvt_tf32(p0);
                af[mt][1] = cvt_tf32(p1);
                af[mt][2] = cvt_tf32(p2);
                af[mt][3] = cvt_tf32(p3);
            }
            const float* bp = cur + (c * 8 + c4) * 72 + q;
#pragma unroll
            for (int n = 0; n < 8; n++) {
                uint32_t b0 = __float_as_uint(bp[n * 8]);
                uint32_t b1 = __float_as_uint(bp[4 * 72 + n * 8]);
                mma_tf32(acc[0][n], af[0][0], af[0][1], af[0][2], af[0][3], b0, b1);
                mma_tf32(acc[1][n], af[1][0], af[1][1], af[1][2], af[1][3], b0, b1);
            }
        }

        if (t < 7) {
#pragma unroll
            for (int it = 0; it < 8; it++) {
                int idx = tid + it * 256;
                *(float4*)&nxt[(idx >> 4) * 72 + (idx & 15) * 4] = pf[it];
            }
        }
        __syncthreads();
    }

    // ---- reduce across js groups (64 slots, stride 69) ----
    float* red = Tb[0];
    int slot = mw * 32 + lane;
    float* accf = &acc[0][0][0];
#pragma unroll
    for (int src = 1; src < 4; src++) {
        if (js == src) {
#pragma unroll
            for (int i = 0; i < 64; i++) red[slot * 69 + i] = accf[i];
#pragma unroll
            for (int i = 0; i < 4; i++) red[slot * 69 + 64 + i] = z[i];
        }
        __syncthreads();
        if (js == 0) {
#pragma unroll
            for (int i = 0; i < 64; i++) accf[i] += red[slot * 69 + i];
#pragma unroll
            for (int i = 0; i < 4; i++) z[i] += red[slot * 69 + 64 + i];
        }
        __syncthreads();
    }

    // ---- write partials (js == 0: 64 threads) ----
    if (js == 0) {
        float* pb = g_part + ((size_t)jsp * BATCH * NTOK + b * NTOK + rbase) * 68;
        // numerators: rows rbase + mt*16 (+8), cols 2*c4 + 8n
#pragma unroll
        for (int mt = 0; mt < 2; mt++) {
            float* pr0 = pb + (size_t)(mt * 16) * 68 + 2 * c4;
            float* pr1 = pb + (size_t)(mt * 16 + 8) * 68 + 2 * c4;
#pragma unroll
            for (int n = 0; n < 8; n++) {
                *(float2*)(pr0 + n * 8) = make_float2(acc[mt][n][0], acc[mt][n][1]);
                *(float2*)(pr1 + n * 8) = make_float2(acc[mt][n][2], acc[mt][n][3]);
            }
        }
        // z shares: row rbase + rr*8, col 64 + c4
#pragma unroll
        for (int rr = 0; rr < 4; rr++)
            pb[(size_t)(rr * 8) * 68 + 64 + c4] = z[rr];
    }
}

// ---------------------------------------------------------------------------
// Kernel 4: combine j-halves, normalize, elu.  32 rows/block, 8 thr/row.
// ---------------------------------------------------------------------------
__global__ void __launch_bounds__(256) k4_comb(float* __restrict__ out) {
    int tid = threadIdx.x;
    int r = tid >> 3, oc = tid & 7;
    size_t row = (size_t)blockIdx.x * 32 + r;
    const float* p0 = g_part + row * 68;
    const float* p1 = g_part + ((size_t)BATCH * NTOK + row) * 68;

    float zt = 0.f;
#pragma unroll
    for (int c = 0; c < 4; c++) zt += p0[64 + c] + p1[64 + c];
    float inv = 1.f / zt;

    float4 a0 = *(const float4*)(p0 + oc * 8);
    float4 a1 = *(const float4*)(p0 + oc * 8 + 4);
    float4 b0 = *(const float4*)(p1 + oc * 8);
    float4 b1 = *(const float4*)(p1 + oc * 8 + 4);
    float4 w0, w1;
    w0.x = eluf((a0.x + b0.x) * inv);
    w0.y = eluf((a0.y + b0.y) * inv);
    w0.z = eluf((a0.z + b0.z) * inv);
    w0.w = eluf((a0.w + b0.w) * inv);
    w1.x = eluf((a1.x + b1.x) * inv);
    w1.y = eluf((a1.y + b1.y) * inv);
    w1.z = eluf((a1.z + b1.z) * inv);
    w1.w = eluf((a1.w + b1.w) * inv);
    float* orow = out + row * 64 + oc * 8;
    *(float4*)orow = w0;
    *(float4*)(orow + 4) = w1;
}

// ---------------------------------------------------------------------------
extern "C" void kernel_launch(void* const* d_in, const int* in_sizes, int n_in,
                              void* d_out, int out_size) {
    const float* h = (const float*)d_in[0];
    const float* W = (const float*)d_in[1];
    const float* a = (const float*)d_in[2];
    float* out = (float*)d_out;

    cudaFuncSetAttribute(k3_attn, cudaFuncAttributeMaxDynamicSharedMemorySize,
                         SMEM3_TOTAL);

    k1_proj<<<(BATCH * NTOK) / 64, 256>>>(h, W, a);
    k2_max<<<1, 256>>>();
    dim3 g3(NTOK / 64, BATCH, 2);
    k3_attn<<<g3, 256, SMEM3_TOTAL>>>();
    k4_comb<<<(BATCH * NTOK) / 32, 256>>>(out);
}

// round 7
// speedup vs baseline: 1.6624x; 1.6624x over previous
#include <cuda_runtime.h>
#include <cuda_fp16.h>
#include <math.h>
#include <stdint.h>

#define BATCH 8
#define NTOK  2048
#define FDIM  64
#define ALPHA 0.2f

// ---------------- scratch (__device__ globals; no allocs allowed) ----------
__device__ __align__(16) __half g_WhT[BATCH * FDIM * NTOK];  // [b][o][j] fp16
__device__ __align__(16) float4 g_suv[BATCH * NTOK];         // {sd, e^sd, e^(a*sd), 0}
__device__ float g_ssrc[BATCH * NTOK];
__device__ float g_maxs[BATCH];

__device__ __forceinline__ float eluf(float x) { return x > 0.f ? x : expm1f(x); }

// pack two floats -> fp16x2 (lo = first, hi = second)
__device__ __forceinline__ uint32_t pack_h2(float lo, float hi) {
    uint32_t r;
    asm("cvt.rn.f16x2.f32 %0, %1, %2;" : "=r"(r) : "f"(hi), "f"(lo));
    return r;
}

__device__ __forceinline__ void mma_f16(float* d, uint32_t a0, uint32_t a1,
                                        uint32_t a2, uint32_t a3,
                                        uint32_t b0, uint32_t b1) {
    asm volatile(
        "mma.sync.aligned.m16n8k16.row.col.f32.f16.f16.f32 "
        "{%0,%1,%2,%3}, {%4,%5,%6,%7}, {%8,%9}, {%0,%1,%2,%3};"
        : "+f"(d[0]), "+f"(d[1]), "+f"(d[2]), "+f"(d[3])
        : "r"(a0), "r"(a1), "r"(a2), "r"(a3), "r"(b0), "r"(b1));
}

// ---------------------------------------------------------------------------
// Kernel 1: Wh = h @ W, scores, suv; WhT (fp16, [b][o][j]) via smem transpose.
// 128 thr, 64 rows/block, 4 rows/thread (32 FMA chains) -- best measured cfg.
// ---------------------------------------------------------------------------
__global__ void __launch_bounds__(128) k1_proj(const float* __restrict__ h,
                                               const float* __restrict__ W,
                                               const float* __restrict__ a) {
    __shared__ float W_s[64 * 64];
    __shared__ float a_s[128];
    __shared__ float h_s[64 * 65];
    __shared__ __align__(16) __half T2[64 * 72];   // [o][r], stride 72 halfs

    int tid = threadIdx.x;
    int row0 = blockIdx.x * 64;
    for (int i = tid; i < 4096; i += 128) W_s[i] = W[i];
    if (tid < 128) a_s[tid] = a[tid];
    for (int i = tid; i < 4096; i += 128) h_s[(i >> 6) * 65 + (i & 63)] = h[row0 * 64 + i];
    __syncthreads();

    int g = tid >> 3, e = tid & 7;       // rows 4g..4g+3; cols e*4 & 32+e*4
    float acc[4][8];
#pragma unroll
    for (int rr = 0; rr < 4; rr++)
#pragma unroll
        for (int i = 0; i < 8; i++) acc[rr][i] = 0.f;

#pragma unroll
    for (int k = 0; k < 64; k++) {
        float4 w0 = *(const float4*)&W_s[k * 64 + e * 4];
        float4 w1 = *(const float4*)&W_s[k * 64 + 32 + e * 4];
#pragma unroll
        for (int rr = 0; rr < 4; rr++) {
            float hv = h_s[(g * 4 + rr) * 65 + k];
            acc[rr][0] = fmaf(hv, w0.x, acc[rr][0]);
            acc[rr][1] = fmaf(hv, w0.y, acc[rr][1]);
            acc[rr][2] = fmaf(hv, w0.z, acc[rr][2]);
            acc[rr][3] = fmaf(hv, w0.w, acc[rr][3]);
            acc[rr][4] = fmaf(hv, w1.x, acc[rr][4]);
            acc[rr][5] = fmaf(hv, w1.y, acc[rr][5]);
            acc[rr][6] = fmaf(hv, w1.z, acc[rr][6]);
            acc[rr][7] = fmaf(hv, w1.w, acc[rr][7]);
        }
    }

#pragma unroll
    for (int rr = 0; rr < 4; rr++) {
        int r = g * 4 + rr;
        int row = row0 + r;
        // transpose into T2[o][r] (fp16)
#pragma unroll
        for (int i = 0; i < 4; i++) {
            T2[(e * 4 + i) * 72 + r]      = __float2half(acc[rr][i]);
            T2[(32 + e * 4 + i) * 72 + r] = __float2half(acc[rr][i + 4]);
        }
        float ps = 0.f, pd = 0.f;
#pragma unroll
        for (int i = 0; i < 4; i++) {
            ps = fmaf(acc[rr][i], a_s[e * 4 + i], ps);
            ps = fmaf(acc[rr][i + 4], a_s[32 + e * 4 + i], ps);
            pd = fmaf(acc[rr][i], a_s[64 + e * 4 + i], pd);
            pd = fmaf(acc[rr][i + 4], a_s[96 + e * 4 + i], pd);
        }
#pragma unroll
        for (int o = 1; o < 8; o <<= 1) {
            ps += __shfl_xor_sync(0xffffffffu, ps, o);
            pd += __shfl_xor_sync(0xffffffffu, pd, o);
        }
        if (e == 0) {
            g_ssrc[row] = ps;
            g_suv[row] = make_float4(pd, expf(pd), expf(ALPHA * pd), 0.f);
        }
    }
    __syncthreads();

    // coalesced WhT write: 512 uint4 (64 o-rows x 8 uint4 of 8 halfs)
    int bb = row0 >> 11;           // batch
    int jb = row0 & 2047;          // j offset within batch
    const uint4* T4 = (const uint4*)T2;
    uint4* dst = (uint4*)(g_WhT + ((size_t)bb * 64) * 2048 + jb);
#pragma unroll
    for (int it = 0; it < 4; it++) {
        int idx = tid + it * 128;            // 0..511
        int o = idx >> 3, j8 = idx & 7;
        dst[o * 256 + j8] = T4[o * 9 + j8];  // 72 halfs = 9 uint4/row
    }
}

// ---------------------------------------------------------------------------
// Kernel 2: per-batch max of s_dst.  Single block, warp per batch.
// ---------------------------------------------------------------------------
__global__ void __launch_bounds__(256) k2_max() {
    int w = threadIdx.x >> 5, lane = threadIdx.x & 31;
    float m = -1e30f;
    for (int j = lane; j < NTOK; j += 32) m = fmaxf(m, g_suv[w * NTOK + j].x);
#pragma unroll
    for (int o = 16; o > 0; o >>= 1)
        m = fmaxf(m, __shfl_xor_sync(0xffffffffu, m, o));
    if (lane == 0) g_maxs[w] = m;
}

// ---------------------------------------------------------------------------
// Kernel 3: fused attention, fp16 m16n8k16 HMMA, double-buffered B tiles.
//   128 CTAs (16 i-tiles x 8 b), 512 thr = 4 m-warps x 4 j-split.
//   Warp: 2 m-tiles (32 rows); per tile (128 j) js handles 2 chunks of 16 j.
//   B_s layout [o][j] fp16, row stride 68 words (136 halfs): bank-conflict-
//   free frag loads (bank = 4*(l/4) + l%4).  A (P) generated in registers,
//   exp-free; packed to fp16x2.  Z scalar.  One __syncthreads per tile.
// ---------------------------------------------------------------------------
#define TB_BYTES   (64 * 272)                 // 64 o-rows x 272B
#define SUV_OFF    (2 * TB_BYTES)
#define SMEM3_TOTAL (SUV_OFF + NTOK * 16)

__global__ void __launch_bounds__(512, 1) k3_attn(float* __restrict__ out) {
    extern __shared__ char smem[];
    uint32_t* Tw[2] = { (uint32_t*)smem, (uint32_t*)(smem + TB_BYTES) };
    float4* suv_s = (float4*)(smem + SUV_OFF);

    int tid = threadIdx.x;
    int lane = tid & 31;
    int wid = tid >> 5;
    int mw = wid & 3, js = wid >> 2;
    int b = blockIdx.y;
    int i0 = blockIdx.x * 128;

    {
        const float4* sg = g_suv + b * NTOK;
        for (int i = tid; i < NTOK; i += 512) suv_s[i] = sg[i];
    }

    int q = lane >> 2, c4 = lane & 3;
    int rbase = i0 + mw * 32 + q;
    float M = g_maxs[b];
    float ssr[4], Ai[4], Bi[4];
#pragma unroll
    for (int rr = 0; rr < 4; rr++) {
        float s = g_ssrc[b * NTOK + rbase + rr * 8];
        float t = s + M;
        float m = t > 0.f ? t : ALPHA * t;
        ssr[rr] = s;
        Ai[rr] = expf(s - m);
        Bi[rr] = expf(ALPHA * s - m);
    }

    float acc[2][8][4];
    float z[4] = {0.f, 0.f, 0.f, 0.f};
#pragma unroll
    for (int mt = 0; mt < 2; mt++)
#pragma unroll
        for (int n = 0; n < 8; n++)
#pragma unroll
            for (int i = 0; i < 4; i++) acc[mt][n][i] = 0.f;

    const uint4* WhT4 = (const uint4*)(g_WhT + (size_t)b * FDIM * NTOK);
    // staging: 1024 uint4 per tile; thread covers idx = tid + it*512
    int so = tid >> 4, sj = tid & 15;   // o-row, uint4-within-row (it adds 32 o)

    // stage tile 0
#pragma unroll
    for (int it = 0; it < 2; it++) {
        int o = so + it * 32;
        uint4 v = WhT4[o * 256 + sj];
        *(uint4*)((char*)Tw[0] + o * 272 + sj * 16) = v;
    }
    __syncthreads();

    for (int t = 0; t < 16; t++) {
        const uint32_t* cur = Tw[t & 1];
        uint32_t* nxt = Tw[(t + 1) & 1];
        uint4 pf[2];
        if (t < 15) {
#pragma unroll
            for (int it = 0; it < 2; it++)
                pf[it] = WhT4[(so + it * 32) * 256 + (t + 1) * 16 + sj];
        }

#pragma unroll
        for (int cc = 0; cc < 2; cc++) {
            int c = js * 2 + cc;
            int jq = t * 128 + c * 16 + 2 * c4;
            float4 s0 = suv_s[jq];
            float4 s1 = suv_s[jq + 1];
            float4 s2 = suv_s[jq + 8];
            float4 s3 = suv_s[jq + 9];
            uint32_t af[2][4];
#pragma unroll
            for (int mt = 0; mt < 2; mt++) {
                int r0 = mt * 2, r1 = mt * 2 + 1;   // rows q+mt*16, q+8+mt*16
                float pa0 = (ssr[r0] + s0.x > 0.f) ? Ai[r0] * s0.y : Bi[r0] * s0.z;
                float pa1 = (ssr[r0] + s1.x > 0.f) ? Ai[r0] * s1.y : Bi[r0] * s1.z;
                float pb0 = (ssr[r1] + s0.x > 0.f) ? Ai[r1] * s0.y : Bi[r1] * s0.z;
                float pb1 = (ssr[r1] + s1.x > 0.f) ? Ai[r1] * s1.y : Bi[r1] * s1.z;
                float pc0 = (ssr[r0] + s2.x > 0.f) ? Ai[r0] * s2.y : Bi[r0] * s2.z;
                float pc1 = (ssr[r0] + s3.x > 0.f) ? Ai[r0] * s3.y : Bi[r0] * s3.z;
                float pd0 = (ssr[r1] + s2.x > 0.f) ? Ai[r1] * s2.y : Bi[r1] * s2.z;
                float pd1 = (ssr[r1] + s3.x > 0.f) ? Ai[r1] * s3.y : Bi[r1] * s3.z;
                z[r0] += (pa0 + pa1) + (pc0 + pc1);
                z[r1] += (pb0 + pb1) + (pd0 + pd1);
                af[mt][0] = pack_h2(pa0, pa1);   // (row q,  k=jq, jq+1)
                af[mt][1] = pack_h2(pb0, pb1);   // (row q+8)
                af[mt][2] = pack_h2(pc0, pc1);   // (row q,  k=jq+8, +9)
                af[mt][3] = pack_h2(pd0, pd1);   // (row q+8)
            }
            // B frags: word (o = n*8 + q, kpair = c*8 + c4), b1 at +4 words
            const uint32_t* bp = cur + q * 68 + c * 8 + c4;
#pragma unroll
            for (int n = 0; n < 8; n++) {
                uint32_t b0 = bp[n * 8 * 68];
                uint32_t b1 = bp[n * 8 * 68 + 4];
                mma_f16(acc[0][n], af[0][0], af[0][1], af[0][2], af[0][3], b0, b1);
                mma_f16(acc[1][n], af[1][0], af[1][1], af[1][2], af[1][3], b0, b1);
            }
        }

        if (t < 15) {
#pragma unroll
            for (int it = 0; it < 2; it++)
                *(uint4*)((char*)nxt + (so + it * 32) * 272 + sj * 16) = pf[it];
        }
        __syncthreads();
    }

    // ---- reduce across js groups (128 slots, stride 69, payload 68) ----
    float* red = (float*)smem;
    int slot = mw * 32 + lane;
    float* accf = &acc[0][0][0];
#pragma unroll
    for (int src = 1; src < 4; src++) {
        if (js == src) {
#pragma unroll
            for (int i = 0; i < 64; i++) red[slot * 69 + i] = accf[i];
#pragma unroll
            for (int i = 0; i < 4; i++) red[slot * 69 + 64 + i] = z[i];
        }
        __syncthreads();
        if (js == 0) {
#pragma unroll
            for (int i = 0; i < 64; i++) accf[i] += red[slot * 69 + i];
#pragma unroll
            for (int i = 0; i < 4; i++) z[i] += red[slot * 69 + 64 + i];
        }
        __syncthreads();
    }

    // ---- epilogue (js == 0) ----
    if (js == 0) {
#pragma unroll
        for (int rr = 0; rr < 4; rr++) {
            z[rr] += __shfl_xor_sync(0xffffffffu, z[rr], 1);
            z[rr] += __shfl_xor_sync(0xffffffffu, z[rr], 2);
        }
        float inv0 = 1.f / z[0], inv1 = 1.f / z[1];
        float inv2 = 1.f / z[2], inv3 = 1.f / z[3];

        float* o0 = out + ((size_t)(b * NTOK + rbase)) * 64 + 2 * c4;
        float* o1 = o0 + 8 * 64;
        float* o2 = o0 + 16 * 64;
        float* o3 = o0 + 24 * 64;
#pragma unroll
        for (int n = 0; n < 8; n++) {
            float2 w0, w1, w2, w3;
            w0.x = eluf(acc[0][n][0] * inv0);
            w0.y = eluf(acc[0][n][1] * inv0);
            w1.x = eluf(acc[0][n][2] * inv1);
            w1.y = eluf(acc[0][n][3] * inv1);
            w2.x = eluf(acc[1][n][0] * inv2);
            w2.y = eluf(acc[1][n][1] * inv2);
            w3.x = eluf(acc[1][n][2] * inv3);
            w3.y = eluf(acc[1][n][3] * inv3);
            *(float2*)(o0 + n * 8) = w0;
            *(float2*)(o1 + n * 8) = w1;
            *(float2*)(o2 + n * 8) = w2;
            *(float2*)(o3 + n * 8) = w3;
        }
    }
}

// ---------------------------------------------------------------------------
extern "C" void kernel_launch(void* const* d_in, const int* in_sizes, int n_in,
                              void* d_out, int out_size) {
    const float* h = (const float*)d_in[0];
    const float* W = (const float*)d_in[1];
    const float* a = (const float*)d_in[2];
    float* out = (float*)d_out;

    cudaFuncSetAttribute(k3_attn, cudaFuncAttributeMaxDynamicSharedMemorySize,
                         SMEM3_TOTAL);

    k1_proj<<<(BATCH * NTOK) / 64, 128>>>(h, W, a);
    k2_max<<<1, 256>>>();
    dim3 g3(NTOK / 128, BATCH);
    k3_attn<<<g3, 512, SMEM3_TOTAL>>>(out);
}

// round 8
// speedup vs baseline: 1.7979x; 1.0816x over previous
#include <cuda_runtime.h>
#include <cuda_fp16.h>
#include <math.h>
#include <stdint.h>

#define BATCH 8
#define NTOK  2048
#define FDIM  64
#define ALPHA 0.2f

// ---------------- scratch (__device__ globals; no allocs allowed) ----------
__device__ __align__(16) __half g_WhT[BATCH * FDIM * NTOK];  // [b][o][j] fp16
__device__ __align__(16) float4 g_suv[BATCH * NTOK];         // {sd, e^sd, e^(a*sd), 0}
__device__ float g_ssrc[BATCH * NTOK];
__device__ float g_maxs[BATCH];

__device__ __forceinline__ float eluf(float x) { return x > 0.f ? x : expm1f(x); }

__device__ __forceinline__ uint32_t smem_u32(const void* p) {
    uint32_t a;
    asm("{ .reg .u64 t; cvta.to.shared.u64 t, %1; cvt.u32.u64 %0, t; }" : "=r"(a) : "l"(p));
    return a;
}

// pack two floats -> fp16x2 (lo half = first arg)  [validated R7]
__device__ __forceinline__ uint32_t pack_h2(float lo, float hi) {
    uint32_t r;
    asm("cvt.rn.f16x2.f32 %0, %1, %2;" : "=r"(r) : "f"(hi), "f"(lo));
    return r;
}

__device__ __forceinline__ void mma_f16(float* d, uint32_t a0, uint32_t a1,
                                        uint32_t a2, uint32_t a3,
                                        uint32_t b0, uint32_t b1) {
    asm volatile(
        "mma.sync.aligned.m16n8k16.row.col.f32.f16.f16.f32 "
        "{%0,%1,%2,%3}, {%4,%5,%6,%7}, {%8,%9}, {%0,%1,%2,%3};"
        : "+f"(d[0]), "+f"(d[1]), "+f"(d[2]), "+f"(d[3])
        : "r"(a0), "r"(a1), "r"(a2), "r"(a3), "r"(b0), "r"(b1));
}

__device__ __forceinline__ void ldm_x4(uint32_t* r, uint32_t addr) {
    asm volatile("ldmatrix.sync.aligned.m8n8.x4.shared.b16 {%0,%1,%2,%3}, [%4];"
                 : "=r"(r[0]), "=r"(r[1]), "=r"(r[2]), "=r"(r[3]) : "r"(addr));
}

// ---------------------------------------------------------------------------
// Kernel 1: Wh = h @ W, scores, suv, WhT(fp16 [b][o][j]).
//   512 thr = 4 k-quarters x (16 row-groups x 8 col-octets); 4 rows/thread,
//   32 FMA chains, k-depth 16; 2-round smem combine (stride 33).
// ---------------------------------------------------------------------------
__global__ void __launch_bounds__(512) k1_proj(const float* __restrict__ h,
                                               const float* __restrict__ W,
                                               const float* __restrict__ a) {
    __shared__ float S[8448];             // W 4096 | a 128 | h 64x65; red overlays
    __shared__ __align__(16) __half T2[64 * 72];
    float* W_s = S;
    float* a_s = S + 4096;
    float* h_s = S + 4224;

    int tid = threadIdx.x;
    int row0 = blockIdx.x * 64;
    for (int i = tid; i < 4096; i += 512) W_s[i] = W[i];
    if (tid < 128) a_s[tid] = a[tid];
    for (int i = tid; i < 4096; i += 512) h_s[(i >> 6) * 65 + (i & 63)] = h[row0 * 64 + i];
    __syncthreads();

    int kh = tid >> 7, sub = tid & 127;
    int g = sub >> 3, e = sub & 7;        // rows 4g..4g+3, cols e*4 & 32+e*4

    float acc[4][8];
#pragma unroll
    for (int rr = 0; rr < 4; rr++)
#pragma unroll
        for (int i = 0; i < 8; i++) acc[rr][i] = 0.f;

    int k0 = kh * 16;
#pragma unroll
    for (int kk = 0; kk < 16; kk++) {
        int k = k0 + kk;
        float4 w0 = *(const float4*)&W_s[k * 64 + e * 4];
        float4 w1 = *(const float4*)&W_s[k * 64 + 32 + e * 4];
#pragma unroll
        for (int rr = 0; rr < 4; rr++) {
            float hv = h_s[(g * 4 + rr) * 65 + k];
            acc[rr][0] = fmaf(hv, w0.x, acc[rr][0]);
            acc[rr][1] = fmaf(hv, w0.y, acc[rr][1]);
            acc[rr][2] = fmaf(hv, w0.z, acc[rr][2]);
            acc[rr][3] = fmaf(hv, w0.w, acc[rr][3]);
            acc[rr][4] = fmaf(hv, w1.x, acc[rr][4]);
            acc[rr][5] = fmaf(hv, w1.y, acc[rr][5]);
            acc[rr][6] = fmaf(hv, w1.z, acc[rr][6]);
            acc[rr][7] = fmaf(hv, w1.w, acc[rr][7]);
        }
    }

    // save a-values before overlay
    float av0[4], av1[4], av2[4], av3[4];
#pragma unroll
    for (int i = 0; i < 4; i++) {
        av0[i] = a_s[e * 4 + i];
        av1[i] = a_s[32 + e * 4 + i];
        av2[i] = a_s[64 + e * 4 + i];
        av3[i] = a_s[96 + e * 4 + i];
    }
    __syncthreads();

    float* red = S;                       // 256 slots x stride 33
    float* accf = &acc[0][0];
    if (kh >= 2) {
#pragma unroll
        for (int i = 0; i < 32; i++) red[((kh - 2) * 128 + sub) * 33 + i] = accf[i];
    }
    __syncthreads();
    if (kh < 2) {
#pragma unroll
        for (int i = 0; i < 32; i++) accf[i] += red[(kh * 128 + sub) * 33 + i];
    }
    __syncthreads();
    if (kh == 1) {
#pragma unroll
        for (int i = 0; i < 32; i++) red[sub * 33 + i] = accf[i];
    }
    __syncthreads();
    if (kh == 0) {
#pragma unroll
        for (int i = 0; i < 32; i++) accf[i] += red[sub * 33 + i];

#pragma unroll
        for (int rr = 0; rr < 4; rr++) {
            int r = g * 4 + rr;
            int row = row0 + r;
#pragma unroll
            for (int i = 0; i < 4; i++) {
                T2[(e * 4 + i) * 72 + r]      = __float2half(acc[rr][i]);
                T2[(32 + e * 4 + i) * 72 + r] = __float2half(acc[rr][i + 4]);
            }
            float ps = 0.f, pd = 0.f;
#pragma unroll
            for (int i = 0; i < 4; i++) {
                ps = fmaf(acc[rr][i], av0[i], ps);
                ps = fmaf(acc[rr][i + 4], av1[i], ps);
                pd = fmaf(acc[rr][i], av2[i], pd);
                pd = fmaf(acc[rr][i + 4], av3[i], pd);
            }
#pragma unroll
            for (int o = 1; o < 8; o <<= 1) {
                ps += __shfl_xor_sync(0xffffffffu, ps, o);
                pd += __shfl_xor_sync(0xffffffffu, pd, o);
            }
            if (e == 0) {
                g_ssrc[row] = ps;
                g_suv[row] = make_float4(pd, expf(pd), expf(ALPHA * pd), 0.f);
            }
        }
    }
    __syncthreads();

    // coalesced WhT write: 512 uint4 (64 o x 8 uint4)
    int bb = row0 >> 11;
    int jb = row0 & 2047;
    const uint4* T4 = (const uint4*)T2;
    uint4* dst = (uint4*)(g_WhT + ((size_t)bb * 64) * 2048 + jb);
    {
        int o = tid >> 3, j8 = tid & 7;
        dst[o * 256 + j8] = T4[o * 9 + j8];
    }
}

// ---------------------------------------------------------------------------
// Kernel 2: per-batch max of s_dst.  8 blocks x 256 thr.
// ---------------------------------------------------------------------------
__global__ void __launch_bounds__(256) k2_max() {
    __shared__ float red[8];
    int b = blockIdx.x, tid = threadIdx.x;
    float m = -1e30f;
    for (int j = tid; j < NTOK; j += 256) m = fmaxf(m, g_suv[b * NTOK + j].x);
#pragma unroll
    for (int o = 16; o > 0; o >>= 1)
        m = fmaxf(m, __shfl_xor_sync(0xffffffffu, m, o));
    if ((tid & 31) == 0) red[tid >> 5] = m;
    __syncthreads();
    if (tid == 0) {
        float r = red[0];
#pragma unroll
        for (int i = 1; i < 8; i++) r = fmaxf(r, red[i]);
        g_maxs[b] = r;
    }
}

// ---------------------------------------------------------------------------
// Kernel 3: fused attention.  p = max(Ai*u, Bi*v) (exact, leaky monotone).
//   B frags via ldmatrix.x4; Z via ones-column with CONSTANT B frag.
//   128 CTAs, 512 thr = 4 m-warps x 4 j-split; B tile [o][jpair] stride 68w.
// ---------------------------------------------------------------------------
#define TBB      17408                    // 64 * 68 * 4 bytes per buffer
#define UOFF     (2 * TBB)
#define VOFF     (UOFF + 8192)
#define SMEM3_TOTAL (VOFF + 8192)

__global__ void __launch_bounds__(512, 1) k3_attn(float* __restrict__ out) {
    extern __shared__ char smem[];
    uint32_t sb = smem_u32(smem);
    float* u_s = (float*)(smem + UOFF);
    float* v_s = (float*)(smem + VOFF);

    int tid = threadIdx.x;
    int lane = tid & 31;
    int wid = tid >> 5;
    int mw = wid & 3, js = wid >> 2;
    int b = blockIdx.y;
    int i0 = blockIdx.x * 128;

    {
        const float4* sg = g_suv + b * NTOK;
        for (int i = tid; i < NTOK; i += 512) {
            float4 s = sg[i];
            u_s[i] = s.y;
            v_s[i] = s.z;
        }
    }

    int q = lane >> 2, c4 = lane & 3;
    int rbase = i0 + mw * 32 + q;
    float M = g_maxs[b];
    float ssr[4], Ai[4], Bi[4];
#pragma unroll
    for (int rr = 0; rr < 4; rr++) {
        float s = g_ssrc[b * NTOK + rbase + rr * 8];
        float t = s + M;
        float m = t > 0.f ? t : ALPHA * t;
        ssr[rr] = s;
        Ai[rr] = expf(s - m);
        Bi[rr] = expf(ALPHA * s - m);
    }

    float acc[2][9][4];
#pragma unroll
    for (int mt = 0; mt < 2; mt++)
#pragma unroll
        for (int n = 0; n < 9; n++)
#pragma unroll
            for (int i = 0; i < 4; i++) acc[mt][n][i] = 0.f;

    uint32_t b_ones = (q == 0) ? 0x3C003C00u : 0u;
    // ldmatrix per-thread row offset (words): matrix rows are o-rows
    uint32_t row_off = ((((lane >> 4) & 1) * 8 + (lane & 7)) * 68u) + ((lane >> 3) & 1) * 4u;

    const uint4* WhT4 = (const uint4*)(g_WhT + (size_t)b * FDIM * NTOK);
    int so = tid >> 4, sj = tid & 15;     // staging: o-row (+32), uint4 col

    // stage tile 0
    {
        uint4* T0 = (uint4*)smem;
#pragma unroll
        for (int it = 0; it < 2; it++) {
            int o = so + it * 32;
            T0[o * 17 + sj] = WhT4[o * 256 + sj];
        }
    }
    __syncthreads();

    for (int t = 0; t < 16; t++) {
        uint32_t cur = sb + (t & 1) * TBB;
        uint4* nxt = (uint4*)(smem + ((t + 1) & 1) * TBB);
        uint4 pf[2];
        if (t < 15) {
#pragma unroll
            for (int it = 0; it < 2; it++)
                pf[it] = WhT4[(so + it * 32) * 256 + (t + 1) * 16 + sj];
        }

#pragma unroll
        for (int cc = 0; cc < 2; cc++) {
            int c = js * 2 + cc;
            int cb = t * 128 + c * 16;
            float2 ua = *(const float2*)&u_s[cb + 2 * c4];
            float2 ub = *(const float2*)&u_s[cb + 8 + 2 * c4];
            float2 va = *(const float2*)&v_s[cb + 2 * c4];
            float2 vb = *(const float2*)&v_s[cb + 8 + 2 * c4];
            uint32_t af[2][4];
#pragma unroll
            for (int mt = 0; mt < 2; mt++) {
                int r0 = mt * 2, r1 = mt * 2 + 1;
                af[mt][0] = pack_h2(fmaxf(Ai[r0] * ua.x, Bi[r0] * va.x),
                                    fmaxf(Ai[r0] * ua.y, Bi[r0] * va.y));
                af[mt][1] = pack_h2(fmaxf(Ai[r1] * ua.x, Bi[r1] * va.x),
                                    fmaxf(Ai[r1] * ua.y, Bi[r1] * va.y));
                af[mt][2] = pack_h2(fmaxf(Ai[r0] * ub.x, Bi[r0] * vb.x),
                                    fmaxf(Ai[r0] * ub.y, Bi[r0] * vb.y));
                af[mt][3] = pack_h2(fmaxf(Ai[r1] * ub.x, Bi[r1] * vb.x),
                                    fmaxf(Ai[r1] * ub.y, Bi[r1] * vb.y));
            }
            // B frags: 4x ldmatrix.x4 covering n-tiles 0..7
            uint32_t bf[4][4];
            uint32_t base = cur + (row_off + (uint32_t)c * 8) * 4;
#pragma unroll
            for (int nn = 0; nn < 4; nn++)
                ldm_x4(bf[nn], base + nn * 4352u);
#pragma unroll
            for (int n = 0; n < 8; n++) {
                uint32_t b0 = bf[n >> 1][(n & 1) * 2];
                uint32_t b1 = bf[n >> 1][(n & 1) * 2 + 1];
                mma_f16(acc[0][n], af[0][0], af[0][1], af[0][2], af[0][3], b0, b1);
                mma_f16(acc[1][n], af[1][0], af[1][1], af[1][2], af[1][3], b0, b1);
            }
            // ones-column (Z): constant B frag
            mma_f16(acc[0][8], af[0][0], af[0][1], af[0][2], af[0][3], b_ones, b_ones);
            mma_f16(acc[1][8], af[1][0], af[1][1], af[1][2], af[1][3], b_ones, b_ones);
        }

        if (t < 15) {
#pragma unroll
            for (int it = 0; it < 2; it++)
                nxt[(so + it * 32) * 17 + sj] = pf[it];
        }
        __syncthreads();
    }

    // ---- reduce across js groups (128 slots, stride 73, payload 72) ----
    float* red = (float*)smem;
    int slot = mw * 32 + lane;
    float* accf = &acc[0][0][0];
#pragma unroll
    for (int src = 1; src < 4; src++) {
        if (js == src) {
#pragma unroll
            for (int i = 0; i < 72; i++) red[slot * 73 + i] = accf[i];
        }
        __syncthreads();
        if (js == 0) {
#pragma unroll
            for (int i = 0; i < 72; i++) accf[i] += red[slot * 73 + i];
        }
        __syncthreads();
    }

    // ---- epilogue (js == 0) ----
    if (js == 0) {
        float z0 = __shfl_sync(0xffffffffu, acc[0][8][0], lane & 28);
        float z1 = __shfl_sync(0xffffffffu, acc[0][8][2], lane & 28);
        float z2 = __shfl_sync(0xffffffffu, acc[1][8][0], lane & 28);
        float z3 = __shfl_sync(0xffffffffu, acc[1][8][2], lane & 28);
        float inv0 = 1.f / z0, inv1 = 1.f / z1;
        float inv2 = 1.f / z2, inv3 = 1.f / z3;

        float* o0 = out + ((size_t)(b * NTOK + rbase)) * 64 + 2 * c4;
        float* o1 = o0 + 8 * 64;
        float* o2 = o0 + 16 * 64;
        float* o3 = o0 + 24 * 64;
#pragma unroll
        for (int n = 0; n < 8; n++) {
            float2 w0, w1, w2, w3;
            w0.x = eluf(acc[0][n][0] * inv0);
            w0.y = eluf(acc[0][n][1] * inv0);
            w1.x = eluf(acc[0][n][2] * inv1);
            w1.y = eluf(acc[0][n][3] * inv1);
            w2.x = eluf(acc[1][n][0] * inv2);
            w2.y = eluf(acc[1][n][1] * inv2);
            w3.x = eluf(acc[1][n][2] * inv3);
            w3.y = eluf(acc[1][n][3] * inv3);
            *(float2*)(o0 + n * 8) = w0;
            *(float2*)(o1 + n * 8) = w1;
            *(float2*)(o2 + n * 8) = w2;
            *(float2*)(o3 + n * 8) = w3;
        }
    }
}

// ---------------------------------------------------------------------------
extern "C" void kernel_launch(void* const* d_in, const int* in_sizes, int n_in,
                              void* d_out, int out_size) {
    const float* h = (const float*)d_in[0];
    const float* W = (const float*)d_in[1];
    const float* a = (const float*)d_in[2];
    float* out = (float*)d_out;

    cudaFuncSetAttribute(k3_attn, cudaFuncAttributeMaxDynamicSharedMemorySize,
                         SMEM3_TOTAL);

    k1_proj<<<(BATCH * NTOK) / 64, 512>>>(h, W, a);
    k2_max<<<BATCH, 256>>>();
    dim3 g3(NTOK / 128, BATCH);
    k3_attn<<<g3, 512, SMEM3_TOTAL>>>(out);
}

// round 10
// speedup vs baseline: 1.9862x; 1.1047x over previous
#include <cuda_runtime.h>
#include <cuda_fp16.h>
#include <math.h>
#include <stdint.h>

#define BATCH 8
#define NTOK  2048
#define FDIM  64
#define ALPHA 0.2f

// ---------------- scratch (__device__ globals; no allocs allowed) ----------
__device__ __align__(16) __half g_WhT[BATCH * FDIM * NTOK];  // [b][o][j] fp16
__device__ __align__(16) float4 g_suv[BATCH * NTOK];         // {sd, e^sd, e^(a*sd), 0}
__device__ float g_ssrc[BATCH * NTOK];
__device__ float g_maxs[BATCH];

__device__ __forceinline__ float eluf(float x) { return x > 0.f ? x : expm1f(x); }

__device__ __forceinline__ uint32_t smem_u32(const void* p) {
    uint32_t a;
    asm("{ .reg .u64 t; cvta.to.shared.u64 t, %1; cvt.u32.u64 %0, t; }" : "=r"(a) : "l"(p));
    return a;
}

__device__ __forceinline__ uint32_t pack_h2(float lo, float hi) {
    uint32_t r;
    asm("cvt.rn.f16x2.f32 %0, %1, %2;" : "=r"(r) : "f"(hi), "f"(lo));
    return r;
}

__device__ __forceinline__ void mma_f16(float* d, uint32_t a0, uint32_t a1,
                                        uint32_t a2, uint32_t a3,
                                        uint32_t b0, uint32_t b1) {
    asm volatile(
        "mma.sync.aligned.m16n8k16.row.col.f32.f16.f16.f32 "
        "{%0,%1,%2,%3}, {%4,%5,%6,%7}, {%8,%9}, {%0,%1,%2,%3};"
        : "+f"(d[0]), "+f"(d[1]), "+f"(d[2]), "+f"(d[3])
        : "r"(a0), "r"(a1), "r"(a2), "r"(a3), "r"(b0), "r"(b1));
}

__device__ __forceinline__ void ldm_x4(uint32_t* r, uint32_t addr) {
    asm volatile("ldmatrix.sync.aligned.m8n8.x4.shared.b16 {%0,%1,%2,%3}, [%4];"
                 : "=r"(r[0]), "=r"(r[1]), "=r"(r[2]), "=r"(r[3]) : "r"(addr));
}

// ---------------------------------------------------------------------------
// Kernel 1: Wh via fp16 HMMA; exact fp32 scores via s = h.(W@a); suv; WhT.
//   grid 256, 128 thr, 64 rows/CTA.  4 warps x 1 m-tile (16 rows).
//   Rows stride 36 words (72 halfs) -> conflict-free ldmatrix.
// ---------------------------------------------------------------------------
__global__ void __launch_bounds__(128) k1_proj(const float* __restrict__ h,
                                               const float* __restrict__ W,
                                               const float* __restrict__ a) {
    __shared__ float a_s[128];
    __shared__ float2 Wa_s[64];                   // {Wa_src, Wa_dst}[k]
    __shared__ __align__(16) __half WT_s[64 * 72];  // [o][k]
    __shared__ __align__(16) __half h_s[64 * 72];   // [j][k]
    __shared__ __align__(16) __half T_s[64 * 72];   // [o][j] (epilogue)

    int tid = threadIdx.x;
    int row0 = blockIdx.x * 64;                   // flat row (b*2048 + j)
    int bb = row0 >> 11;
    int jbase = row0 & 2047;

    if (tid < 128) a_s[tid] = a[tid];
    __syncthreads();

    // ---- W transpose (fp16) + Wa = W @ a (fp32, exact path for scores) ----
    {
        int k = tid >> 1, oh = tid & 1;
        const float4* wr = (const float4*)(W + k * 64 + oh * 32);
        float pws = 0.f, pwd = 0.f;
#pragma unroll
        for (int f = 0; f < 8; f++) {
            float4 v = wr[f];
            int o = oh * 32 + f * 4;
            WT_s[(o + 0) * 72 + k] = __float2half(v.x);
            WT_s[(o + 1) * 72 + k] = __float2half(v.y);
            WT_s[(o + 2) * 72 + k] = __float2half(v.z);
            WT_s[(o + 3) * 72 + k] = __float2half(v.w);
            pws += v.x * a_s[o] + v.y * a_s[o + 1] + v.z * a_s[o + 2] + v.w * a_s[o + 3];
            pwd += v.x * a_s[64 + o] + v.y * a_s[65 + o] + v.z * a_s[66 + o] + v.w * a_s[67 + o];
        }
        pws += __shfl_xor_sync(0xffffffffu, pws, 1);
        pwd += __shfl_xor_sync(0xffffffffu, pwd, 1);
        if (oh == 0) Wa_s[k] = make_float2(pws, pwd);
    }

    // ---- h load (fp32, kept in regs for exact dots) ----
    int r = tid >> 1, hf = tid & 1;
    float4 hv[8];
    {
        const float4* hrow = (const float4*)(h + (size_t)(row0 + r) * 64 + hf * 32);
#pragma unroll
        for (int f = 0; f < 8; f++) hv[f] = hrow[f];
    }
    __syncthreads();   // Wa_s ready

    // ---- exact dots + fp16 h_s store ----
    {
        float ps = 0.f, pd = 0.f;
        __half2* hs2 = (__half2*)(h_s + r * 72 + hf * 32);
#pragma unroll
        for (int f = 0; f < 8; f++) {
            float4 v = hv[f];
            int k = hf * 32 + f * 4;
            float2 w0 = Wa_s[k], w1 = Wa_s[k + 1], w2 = Wa_s[k + 2], w3 = Wa_s[k + 3];
            ps += v.x * w0.x + v.y * w1.x + v.z * w2.x + v.w * w3.x;
            pd += v.x * w0.y + v.y * w1.y + v.z * w2.y + v.w * w3.y;
            hs2[f * 2]     = __floats2half2_rn(v.x, v.y);
            hs2[f * 2 + 1] = __floats2half2_rn(v.z, v.w);
        }
        ps += __shfl_xor_sync(0xffffffffu, ps, 1);
        pd += __shfl_xor_sync(0xffffffffu, pd, 1);
        if (hf == 0) {
            g_ssrc[row0 + r] = ps;
            g_suv[row0 + r] = make_float4(pd, expf(pd), expf(ALPHA * pd), 0.f);
        }
    }
    __syncthreads();

    // ---- MMA: Wh tile = h_s @ WT_s^T ; warp w -> rows w*16.. ----
    int w = tid >> 5, lane = tid & 31;
    uint32_t hs_b = smem_u32(h_s);
    uint32_t wt_b = smem_u32(WT_s);
    // A: m0=(r-lo,k-lo) m1=(r-hi,k-lo) m2=(r-lo,k-hi) m3=(r-hi,k-hi)
    uint32_t aoff = ((w * 16 + ((lane >> 3) & 1) * 8 + (lane & 7)) * 36 +
                     ((lane >> 4) & 1) * 4) * 4;
    // B: m0=(o-oct0,k-lo) m1=(o-oct0,k-hi) m2=(o-oct1,k-lo) m3=(o-oct1,k-hi)
    uint32_t boff = ((((lane >> 4) & 1) * 8 + (lane & 7)) * 36 +
                     ((lane >> 3) & 1) * 4) * 4;

    float acc[8][4];
#pragma unroll
    for (int n = 0; n < 8; n++)
#pragma unroll
        for (int i = 0; i < 4; i++) acc[n][i] = 0.f;

#pragma unroll
    for (int kk = 0; kk < 4; kk++) {
        uint32_t av[4];
        ldm_x4(av, hs_b + aoff + kk * 32);
#pragma unroll
        for (int nn = 0; nn < 4; nn++) {
            uint32_t bv[4];
            ldm_x4(bv, wt_b + boff + nn * 2304 + kk * 32);
            mma_f16(acc[2 * nn],     av[0], av[1], av[2], av[3], bv[0], bv[1]);
            mma_f16(acc[2 * nn + 1], av[0], av[1], av[2], av[3], bv[2], bv[3]);
        }
    }

    // ---- transpose acc -> T_s[o][j] fp16 ----
    {
        int q = lane >> 2, c4 = lane & 3;
        int jr = w * 16 + q;
#pragma unroll
        for (int n = 0; n < 8; n++) {
            int o = n * 8 + 2 * c4;
            T_s[o * 72 + jr]           = __float2half(acc[n][0]);
            T_s[(o + 1) * 72 + jr]     = __float2half(acc[n][1]);
            T_s[o * 72 + jr + 8]       = __float2half(acc[n][2]);
            T_s[(o + 1) * 72 + jr + 8] = __float2half(acc[n][3]);
        }
    }
    __syncthreads();

    // ---- coalesced WhT store: 512 uint4 ----
    {
        const uint4* T4 = (const uint4*)T_s;      // row stride 9 uint4
        uint4* dst = (uint4*)(g_WhT + (size_t)bb * FDIM * NTOK + jbase);
#pragma unroll
        for (int it = 0; it < 4; it++) {
            int idx = tid + it * 128;
            int o = idx >> 3, u4 = idx & 7;
            dst[o * 256 + u4] = T4[o * 9 + u4];
        }
    }
}

// ---------------------------------------------------------------------------
// Kernel 2: per-batch max of s_dst.  8 blocks x 256 thr.
// ---------------------------------------------------------------------------
__global__ void __launch_bounds__(256) k2_max() {
    __shared__ float red[8];
    int b = blockIdx.x, tid = threadIdx.x;
    float m = -1e30f;
    for (int j = tid; j < NTOK; j += 256) m = fmaxf(m, g_suv[b * NTOK + j].x);
#pragma unroll
    for (int o = 16; o > 0; o >>= 1)
        m = fmaxf(m, __shfl_xor_sync(0xffffffffu, m, o));
    if ((tid & 31) == 0) red[tid >> 5] = m;
    __syncthreads();
    if (tid == 0) {
        float r = red[0];
#pragma unroll
        for (int i = 1; i < 8; i++) r = fmaxf(r, red[i]);
        g_maxs[b] = r;
    }
}

// ---------------------------------------------------------------------------
// Kernel 3: fused attention.  p = max(Ai*u, Bi*v); ldmatrix B; ones-col Z.
//   grid 256 (32 i-tiles x 8 b), 256 thr = 2 m-warps x 4 j-split.
//   2 CTAs/SM; B tile [o][j] fp16 stride 68 words, double buffered.
// ---------------------------------------------------------------------------
#define TBB      17408                    // 64 * 68 * 4 bytes per buffer
#define UOFF     (2 * TBB)
#define VOFF     (UOFF + 8192)
#define SMEM3_TOTAL (VOFF + 8192)

__global__ void __launch_bounds__(256, 2) k3_attn(float* __restrict__ out) {
    extern __shared__ char smem[];
    uint32_t sb = smem_u32(smem);
    float* u_s = (float*)(smem + UOFF);
    float* v_s = (float*)(smem + VOFF);

    int tid = threadIdx.x;
    int lane = tid & 31;
    int wid = tid >> 5;
    int mw = wid & 1, js = wid >> 1;
    int b = blockIdx.y;
    int i0 = blockIdx.x * 64;

    {
        const float4* sg = g_suv + b * NTOK;
        for (int i = tid; i < NTOK; i += 256) {
            float4 s = sg[i];
            u_s[i] = s.y;
            v_s[i] = s.z;
        }
    }

    int q = lane >> 2, c4 = lane & 3;
    int rbase = i0 + mw * 32 + q;
    float M = g_maxs[b];
    float ssr[4], Ai[4], Bi[4];
#pragma unroll
    for (int rr = 0; rr < 4; rr++) {
        float s = g_ssrc[b * NTOK + rbase + rr * 8];
        float t = s + M;
        float m = t > 0.f ? t : ALPHA * t;
        ssr[rr] = s;
        Ai[rr] = expf(s - m);
        Bi[rr] = expf(ALPHA * s - m);
    }

    float acc[2][9][4];
#pragma unroll
    for (int mt = 0; mt < 2; mt++)
#pragma unroll
        for (int n = 0; n < 9; n++)
#pragma unroll
            for (int i = 0; i < 4; i++) acc[mt][n][i] = 0.f;

    uint32_t b_ones = (q == 0) ? 0x3C003C00u : 0u;
    uint32_t row_off = ((((lane >> 4) & 1) * 8 + (lane & 7)) * 68u) + ((lane >> 3) & 1) * 4u;

    const uint4* WhT4 = (const uint4*)(g_WhT + (size_t)b * FDIM * NTOK);

    // stage tile 0
    {
        uint4* T0 = (uint4*)smem;
#pragma unroll
        for (int it = 0; it < 4; it++) {
            int idx = tid + it * 256;
            int o = idx >> 4, sj = idx & 15;
            T0[o * 17 + sj] = WhT4[o * 256 + sj];
        }
    }
    __syncthreads();

    for (int t = 0; t < 16; t++) {
        uint32_t cur = sb + (t & 1) * TBB;
        uint4* nxt = (uint4*)(smem + ((t + 1) & 1) * TBB);
        uint4 pf[4];
        if (t < 15) {
#pragma unroll
            for (int it = 0; it < 4; it++) {
                int idx = tid + it * 256;
                pf[it] = WhT4[(idx >> 4) * 256 + (t + 1) * 16 + (idx & 15)];
            }
        }

#pragma unroll
        for (int cc = 0; cc < 2; cc++) {
            int c = js * 2 + cc;
            int cb = t * 128 + c * 16;
            float2 ua = *(const float2*)&u_s[cb + 2 * c4];
            float2 ub = *(const float2*)&u_s[cb + 8 + 2 * c4];
            float2 va = *(const float2*)&v_s[cb + 2 * c4];
            float2 vb = *(const float2*)&v_s[cb + 8 + 2 * c4];
            uint32_t af[2][4];
#pragma unroll
            for (int mt = 0; mt < 2; mt++) {
                int r0 = mt * 2, r1 = mt * 2 + 1;
                af[mt][0] = pack_h2(fmaxf(Ai[r0] * ua.x, Bi[r0] * va.x),
                                    fmaxf(Ai[r0] * ua.y, Bi[r0] * va.y));
                af[mt][1] = pack_h2(fmaxf(Ai[r1] * ua.x, Bi[r1] * va.x),
                                    fmaxf(Ai[r1] * ua.y, Bi[r1] * va.y));
                af[mt][2] = pack_h2(fmaxf(Ai[r0] * ub.x, Bi[r0] * vb.x),
                                    fmaxf(Ai[r0] * ub.y, Bi[r0] * vb.y));
                af[mt][3] = pack_h2(fmaxf(Ai[r1] * ub.x, Bi[r1] * vb.x),
                                    fmaxf(Ai[r1] * ub.y, Bi[r1] * vb.y));
            }
            uint32_t bf[4][4];
            uint32_t base = cur + (row_off + (uint32_t)c * 8) * 4;
#pragma unroll
            for (int nn = 0; nn < 4; nn++)
                ldm_x4(bf[nn], base + nn * 4352u);
#pragma unroll
            for (int n = 0; n < 8; n++) {
                uint32_t b0 = bf[n >> 1][(n & 1) * 2];
                uint32_t b1 = bf[n >> 1][(n & 1) * 2 + 1];
                mma_f16(acc[0][n], af[0][0], af[0][1], af[0][2], af[0][3], b0, b1);
                mma_f16(acc[1][n], af[1][0], af[1][1], af[1][2], af[1][3], b0, b1);
            }
            mma_f16(acc[0][8], af[0][0], af[0][1], af[0][2], af[0][3], b_ones, b_ones);
            mma_f16(acc[1][8], af[1][0], af[1][1], af[1][2], af[1][3], b_ones, b_ones);
        }

        if (t < 15) {
#pragma unroll
            for (int it = 0; it < 4; it++) {
                int idx = tid + it * 256;
                nxt[(idx >> 4) * 17 + (idx & 15)] = pf[it];
            }
        }
        __syncthreads();
    }

    // ---- reduce across js groups (64 slots, stride 73, payload 72) ----
    float* red = (float*)smem;
    int slot = mw * 32 + lane;
    float* accf = &acc[0][0][0];
#pragma unroll
    for (int src = 1; src < 4; src++) {
        if (js == src) {
#pragma unroll
            for (int i = 0; i < 72; i++) red[slot * 73 + i] = accf[i];
        }
        __syncthreads();
        if (js == 0) {
#pragma unroll
            for (int i = 0; i < 72; i++) accf[i] += red[slot * 73 + i];
        }
        __syncthreads();
    }

    // ---- epilogue (js == 0) ----
    if (js == 0) {
        float z0 = __shfl_sync(0xffffffffu, acc[0][8][0], lane & 28);
        float z1 = __shfl_sync(0xffffffffu, acc[0][8][2], lane & 28);
        float z2 = __shfl_sync(0xffffffffu, acc[1][8][0], lane & 28);
        float z3 = __shfl_sync(0xffffffffu, acc[1][8][2], lane & 28);
        float inv0 = 1.f / z0, inv1 = 1.f / z1;
        float inv2 = 1.f / z2, inv3 = 1.f / z3;

        float* o0 = out + ((size_t)(b * NTOK + rbase)) * 64 + 2 * c4;
        float* o1 = o0 + 8 * 64;
        float* o2 = o0 + 16 * 64;
        float* o3 = o0 + 24 * 64;
#pragma unroll
        for (int n = 0; n < 8; n++) {
            float2 w0, w1, w2, w3;
            w0.x = eluf(acc[0][n][0] * inv0);
            w0.y = eluf(acc[0][n][1] * inv0);
            w1.x = eluf(acc[0][n][2] * inv1);
            w1.y = eluf(acc[0][n][3] * inv1);
            w2.x = eluf(acc[1][n][0] * inv2);
            w2.y = eluf(acc[1][n][1] * inv2);
            w3.x = eluf(acc[1][n][2] * inv3);
            w3.y = eluf(acc[1][n][3] * inv3);
            *(float2*)(o0 + n * 8) = w0;
            *(float2*)(o1 + n * 8) = w1;
            *(float2*)(o2 + n * 8) = w2;
            *(float2*)(o3 + n * 8) = w3;
        }
    }
}

// ---------------------------------------------------------------------------
extern "C" void kernel_launch(void* const* d_in, const int* in_sizes, int n_in,
                              void* d_out, int out_size) {
    const float* h = (const float*)d_in[0];
    const float* W = (const float*)d_in[1];
    const float* a = (const float*)d_in[2];
    float* out = (float*)d_out;

    cudaFuncSetAttribute(k3_attn, cudaFuncAttributeMaxDynamicSharedMemorySize,
                         SMEM3_TOTAL);

    k1_proj<<<(BATCH * NTOK) / 64, 128>>>(h, W, a);
    k2_max<<<BATCH, 256>>>();
    dim3 g3(NTOK / 64, BATCH);
    k3_attn<<<g3, 256, SMEM3_TOTAL>>>(out);
}

// round 11
// speedup vs baseline: 2.0843x; 1.0494x over previous
#include <cuda_runtime.h>
#include <cuda_fp16.h>
#include <math.h>
#include <stdint.h>

#define BATCH 8
#define NTOK  2048
#define FDIM  64
#define ALPHA 0.2f

// ---------------- scratch (__device__ globals; no allocs allowed) ----------
__device__ __align__(16) __half g_WhT[BATCH * FDIM * NTOK];  // [b][o][j] fp16
__device__ __align__(16) float4 g_suv[BATCH * NTOK];         // {sd, e^sd, e^(a*sd), 0}
__device__ float g_ssrc[BATCH * NTOK];
__device__ float g_maxs[BATCH];

__device__ __forceinline__ float eluf(float x) { return x > 0.f ? x : expm1f(x); }

__device__ __forceinline__ uint32_t smem_u32(const void* p) {
    uint32_t a;
    asm("{ .reg .u64 t; cvta.to.shared.u64 t, %1; cvt.u32.u64 %0, t; }" : "=r"(a) : "l"(p));
    return a;
}

__device__ __forceinline__ uint32_t pack_h2(float lo, float hi) {
    uint32_t r;
    asm("cvt.rn.f16x2.f32 %0, %1, %2;" : "=r"(r) : "f"(hi), "f"(lo));
    return r;
}

__device__ __forceinline__ void mma_f16(float* d, uint32_t a0, uint32_t a1,
                                        uint32_t a2, uint32_t a3,
                                        uint32_t b0, uint32_t b1) {
    asm volatile(
        "mma.sync.aligned.m16n8k16.row.col.f32.f16.f16.f32 "
        "{%0,%1,%2,%3}, {%4,%5,%6,%7}, {%8,%9}, {%0,%1,%2,%3};"
        : "+f"(d[0]), "+f"(d[1]), "+f"(d[2]), "+f"(d[3])
        : "r"(a0), "r"(a1), "r"(a2), "r"(a3), "r"(b0), "r"(b1));
}

__device__ __forceinline__ void ldm_x4(uint32_t* r, uint32_t addr) {
    asm volatile("ldmatrix.sync.aligned.m8n8.x4.shared.b16 {%0,%1,%2,%3}, [%4];"
                 : "=r"(r[0]), "=r"(r[1]), "=r"(r[2]), "=r"(r[3]) : "r"(addr));
}

// ---------------------------------------------------------------------------
// Kernel 1 (R10, measured 7.9us): Wh via fp16 HMMA; exact fp32 scores via
// s = h.(W@a); suv; WhT.  grid 256, 128 thr, 64 rows/CTA.
// ---------------------------------------------------------------------------
__global__ void __launch_bounds__(128) k1_proj(const float* __restrict__ h,
                                               const float* __restrict__ W,
                                               const float* __restrict__ a) {
    __shared__ float a_s[128];
    __shared__ float2 Wa_s[64];                   // {Wa_src, Wa_dst}[k]
    __shared__ __align__(16) __half WT_s[64 * 72];  // [o][k]
    __shared__ __align__(16) __half h_s[64 * 72];   // [j][k]
    __shared__ __align__(16) __half T_s[64 * 72];   // [o][j] (epilogue)

    int tid = threadIdx.x;
    int row0 = blockIdx.x * 64;                   // flat row (b*2048 + j)
    int bb = row0 >> 11;
    int jbase = row0 & 2047;

    if (tid < 128) a_s[tid] = a[tid];
    __syncthreads();

    // ---- W transpose (fp16) + Wa = W @ a (fp32, exact path for scores) ----
    {
        int k = tid >> 1, oh = tid & 1;
        const float4* wr = (const float4*)(W + k * 64 + oh * 32);
        float pws = 0.f, pwd = 0.f;
#pragma unroll
        for (int f = 0; f < 8; f++) {
            float4 v = wr[f];
            int o = oh * 32 + f * 4;
            WT_s[(o + 0) * 72 + k] = __float2half(v.x);
            WT_s[(o + 1) * 72 + k] = __float2half(v.y);
            WT_s[(o + 2) * 72 + k] = __float2half(v.z);
            WT_s[(o + 3) * 72 + k] = __float2half(v.w);
            pws += v.x * a_s[o] + v.y * a_s[o + 1] + v.z * a_s[o + 2] + v.w * a_s[o + 3];
            pwd += v.x * a_s[64 + o] + v.y * a_s[65 + o] + v.z * a_s[66 + o] + v.w * a_s[67 + o];
        }
        pws += __shfl_xor_sync(0xffffffffu, pws, 1);
        pwd += __shfl_xor_sync(0xffffffffu, pwd, 1);
        if (oh == 0) Wa_s[k] = make_float2(pws, pwd);
    }

    // ---- h load (fp32, kept in regs for exact dots) ----
    int r = tid >> 1, hf = tid & 1;
    float4 hv[8];
    {
        const float4* hrow = (const float4*)(h + (size_t)(row0 + r) * 64 + hf * 32);
#pragma unroll
        for (int f = 0; f < 8; f++) hv[f] = hrow[f];
    }
    __syncthreads();   // Wa_s ready

    // ---- exact dots + fp16 h_s store ----
    {
        float ps = 0.f, pd = 0.f;
        __half2* hs2 = (__half2*)(h_s + r * 72 + hf * 32);
#pragma unroll
        for (int f = 0; f < 8; f++) {
            float4 v = hv[f];
            int k = hf * 32 + f * 4;
            float2 w0 = Wa_s[k], w1 = Wa_s[k + 1], w2 = Wa_s[k + 2], w3 = Wa_s[k + 3];
            ps += v.x * w0.x + v.y * w1.x + v.z * w2.x + v.w * w3.x;
            pd += v.x * w0.y + v.y * w1.y + v.z * w2.y + v.w * w3.y;
            hs2[f * 2]     = __floats2half2_rn(v.x, v.y);
            hs2[f * 2 + 1] = __floats2half2_rn(v.z, v.w);
        }
        ps += __shfl_xor_sync(0xffffffffu, ps, 1);
        pd += __shfl_xor_sync(0xffffffffu, pd, 1);
        if (hf == 0) {
            g_ssrc[row0 + r] = ps;
            g_suv[row0 + r] = make_float4(pd, expf(pd), expf(ALPHA * pd), 0.f);
        }
    }
    __syncthreads();

    // ---- MMA: Wh tile = h_s @ WT_s^T ; warp w -> rows w*16.. ----
    int w = tid >> 5, lane = tid & 31;
    uint32_t hs_b = smem_u32(h_s);
    uint32_t wt_b = smem_u32(WT_s);
    uint32_t aoff = ((w * 16 + ((lane >> 3) & 1) * 8 + (lane & 7)) * 36 +
                     ((lane >> 4) & 1) * 4) * 4;
    uint32_t boff = ((((lane >> 4) & 1) * 8 + (lane & 7)) * 36 +
                     ((lane >> 3) & 1) * 4) * 4;

    float acc[8][4];
#pragma unroll
    for (int n = 0; n < 8; n++)
#pragma unroll
        for (int i = 0; i < 4; i++) acc[n][i] = 0.f;

#pragma unroll
    for (int kk = 0; kk < 4; kk++) {
        uint32_t av[4];
        ldm_x4(av, hs_b + aoff + kk * 32);
#pragma unroll
        for (int nn = 0; nn < 4; nn++) {
            uint32_t bv[4];
            ldm_x4(bv, wt_b + boff + nn * 2304 + kk * 32);
            mma_f16(acc[2 * nn],     av[0], av[1], av[2], av[3], bv[0], bv[1]);
            mma_f16(acc[2 * nn + 1], av[0], av[1], av[2], av[3], bv[2], bv[3]);
        }
    }

    // ---- transpose acc -> T_s[o][j] fp16 ----
    {
        int q = lane >> 2, c4 = lane & 3;
        int jr = w * 16 + q;
#pragma unroll
        for (int n = 0; n < 8; n++) {
            int o = n * 8 + 2 * c4;
            T_s[o * 72 + jr]           = __float2half(acc[n][0]);
            T_s[(o + 1) * 72 + jr]     = __float2half(acc[n][1]);
            T_s[o * 72 + jr + 8]       = __float2half(acc[n][2]);
            T_s[(o + 1) * 72 + jr + 8] = __float2half(acc[n][3]);
        }
    }
    __syncthreads();

    // ---- coalesced WhT store: 512 uint4 ----
    {
        const uint4* T4 = (const uint4*)T_s;      // row stride 9 uint4
        uint4* dst = (uint4*)(g_WhT + (size_t)bb * FDIM * NTOK + jbase);
#pragma unroll
        for (int it = 0; it < 4; it++) {
            int idx = tid + it * 128;
            int o = idx >> 3, u4 = idx & 7;
            dst[o * 256 + u4] = T4[o * 9 + u4];
        }
    }
}

// ---------------------------------------------------------------------------
// Kernel 2: per-batch max of s_dst.  8 blocks x 256 thr.
// ---------------------------------------------------------------------------
__global__ void __launch_bounds__(256) k2_max() {
    __shared__ float red[8];
    int b = blockIdx.x, tid = threadIdx.x;
    float m = -1e30f;
    for (int j = tid; j < NTOK; j += 256) m = fmaxf(m, g_suv[b * NTOK + j].x);
#pragma unroll
    for (int o = 16; o > 0; o >>= 1)
        m = fmaxf(m, __shfl_xor_sync(0xffffffffu, m, o));
    if ((tid & 31) == 0) red[tid >> 5] = m;
    __syncthreads();
    if (tid == 0) {
        float r = red[0];
#pragma unroll
        for (int i = 1; i < 8; i++) r = fmaxf(r, red[i]);
        g_maxs[b] = r;
    }
}

// ---------------------------------------------------------------------------
// Kernel 3 (R8 shape, measured ~21us): fused attention.
//   p = max(Ai*u, Bi*v); ldmatrix B; ones-col Z with constant B frag.
//   128 CTAs (16 i-tiles x 8 b), 512 thr = 4 m-warps x 4 j-split,
//   2 m-tiles/warp (32 rows); B tile [o][j] fp16 stride 68 words, dbl-buffered.
// ---------------------------------------------------------------------------
#define TBB      17408                    // 64 * 68 * 4 bytes per buffer
#define UOFF     (2 * TBB)
#define VOFF     (UOFF + 8192)
#define SMEM3_TOTAL (VOFF + 8192)

__global__ void __launch_bounds__(512, 1) k3_attn(float* __restrict__ out) {
    extern __shared__ char smem[];
    uint32_t sb = smem_u32(smem);
    float* u_s = (float*)(smem + UOFF);
    float* v_s = (float*)(smem + VOFF);

    int tid = threadIdx.x;
    int lane = tid & 31;
    int wid = tid >> 5;
    int mw = wid & 3, js = wid >> 2;
    int b = blockIdx.y;
    int i0 = blockIdx.x * 128;

    {
        const float4* sg = g_suv + b * NTOK;
        for (int i = tid; i < NTOK; i += 512) {
            float4 s = sg[i];
            u_s[i] = s.y;
            v_s[i] = s.z;
        }
    }

    int q = lane >> 2, c4 = lane & 3;
    int rbase = i0 + mw * 32 + q;
    float M = g_maxs[b];
    float ssr[4], Ai[4], Bi[4];
#pragma unroll
    for (int rr = 0; rr < 4; rr++) {
        float s = g_ssrc[b * NTOK + rbase + rr * 8];
        float t = s + M;
        float m = t > 0.f ? t : ALPHA * t;
        ssr[rr] = s;
        Ai[rr] = expf(s - m);
        Bi[rr] = expf(ALPHA * s - m);
    }

    float acc[2][9][4];
#pragma unroll
    for (int mt = 0; mt < 2; mt++)
#pragma unroll
        for (int n = 0; n < 9; n++)
#pragma unroll
            for (int i = 0; i < 4; i++) acc[mt][n][i] = 0.f;

    uint32_t b_ones = (q == 0) ? 0x3C003C00u : 0u;
    uint32_t row_off = ((((lane >> 4) & 1) * 8 + (lane & 7)) * 68u) + ((lane >> 3) & 1) * 4u;

    const uint4* WhT4 = (const uint4*)(g_WhT + (size_t)b * FDIM * NTOK);
    int so = tid >> 4, sj = tid & 15;     // staging: o-row (+32), uint4 col

    // stage tile 0
    {
        uint4* T0 = (uint4*)smem;
#pragma unroll
        for (int it = 0; it < 2; it++) {
            int o = so + it * 32;
            T0[o * 17 + sj] = WhT4[o * 256 + sj];
        }
    }
    __syncthreads();

    for (int t = 0; t < 16; t++) {
        uint32_t cur = sb + (t & 1) * TBB;
        uint4* nxt = (uint4*)(smem + ((t + 1) & 1) * TBB);
        uint4 pf[2];
        if (t < 15) {
#pragma unroll
            for (int it = 0; it < 2; it++)
                pf[it] = WhT4[(so + it * 32) * 256 + (t + 1) * 16 + sj];
        }

#pragma unroll
        for (int cc = 0; cc < 2; cc++) {
            int c = js * 2 + cc;
            int cb = t * 128 + c * 16;
            float2 ua = *(const float2*)&u_s[cb + 2 * c4];
            float2 ub = *(const float2*)&u_s[cb + 8 + 2 * c4];
            float2 va = *(const float2*)&v_s[cb + 2 * c4];
            float2 vb = *(const float2*)&v_s[cb + 8 + 2 * c4];
            uint32_t af[2][4];
#pragma unroll
            for (int mt = 0; mt < 2; mt++) {
                int r0 = mt * 2, r1 = mt * 2 + 1;
                af[mt][0] = pack_h2(fmaxf(Ai[r0] * ua.x, Bi[r0] * va.x),
                                    fmaxf(Ai[r0] * ua.y, Bi[r0] * va.y));
                af[mt][1] = pack_h2(fmaxf(Ai[r1] * ua.x, Bi[r1] * va.x),
                                    fmaxf(Ai[r1] * ua.y, Bi[r1] * va.y));
                af[mt][2] = pack_h2(fmaxf(Ai[r0] * ub.x, Bi[r0] * vb.x),
                                    fmaxf(Ai[r0] * ub.y, Bi[r0] * vb.y));
                af[mt][3] = pack_h2(fmaxf(Ai[r1] * ub.x, Bi[r1] * vb.x),
                                    fmaxf(Ai[r1] * ub.y, Bi[r1] * vb.y));
            }
            uint32_t bf[4][4];
            uint32_t base = cur + (row_off + (uint32_t)c * 8) * 4;
#pragma unroll
            for (int nn = 0; nn < 4; nn++)
                ldm_x4(bf[nn], base + nn * 4352u);
#pragma unroll
            for (int n = 0; n < 8; n++) {
                uint32_t b0 = bf[n >> 1][(n & 1) * 2];
                uint32_t b1 = bf[n >> 1][(n & 1) * 2 + 1];
                mma_f16(acc[0][n], af[0][0], af[0][1], af[0][2], af[0][3], b0, b1);
                mma_f16(acc[1][n], af[1][0], af[1][1], af[1][2], af[1][3], b0, b1);
            }
            mma_f16(acc[0][8], af[0][0], af[0][1], af[0][2], af[0][3], b_ones, b_ones);
            mma_f16(acc[1][8], af[1][0], af[1][1], af[1][2], af[1][3], b_ones, b_ones);
        }

        if (t < 15) {
#pragma unroll
            for (int it = 0; it < 2; it++)
                nxt[(so + it * 32) * 17 + sj] = pf[it];
        }
        __syncthreads();
    }

    // ---- reduce across js groups (128 slots, stride 73, payload 72) ----
    float* red = (float*)smem;
    int slot = mw * 32 + lane;
    float* accf = &acc[0][0][0];
#pragma unroll
    for (int src = 1; src < 4; src++) {
        if (js == src) {
#pragma unroll
            for (int i = 0; i < 72; i++) red[slot * 73 + i] = accf[i];
        }
        __syncthreads();
        if (js == 0) {
#pragma unroll
            for (int i = 0; i < 72; i++) accf[i] += red[slot * 73 + i];
        }
        __syncthreads();
    }

    // ---- epilogue (js == 0) ----
    if (js == 0) {
        float z0 = __shfl_sync(0xffffffffu, acc[0][8][0], lane & 28);
        float z1 = __shfl_sync(0xffffffffu, acc[0][8][2], lane & 28);
        float z2 = __shfl_sync(0xffffffffu, acc[1][8][0], lane & 28);
        float z3 = __shfl_sync(0xffffffffu, acc[1][8][2], lane & 28);
        float inv0 = 1.f / z0, inv1 = 1.f / z1;
        float inv2 = 1.f / z2, inv3 = 1.f / z3;

        float* o0 = out + ((size_t)(b * NTOK + rbase)) * 64 + 2 * c4;
        float* o1 = o0 + 8 * 64;
        float* o2 = o0 + 16 * 64;
        float* o3 = o0 + 24 * 64;
#pragma unroll
        for (int n = 0; n < 8; n++) {
            float2 w0, w1, w2, w3;
            w0.x = eluf(acc[0][n][0] * inv0);
            w0.y = eluf(acc[0][n][1] * inv0);
            w1.x = eluf(acc[0][n][2] * inv1);
            w1.y = eluf(acc[0][n][3] * inv1);
            w2.x = eluf(acc[1][n][0] * inv2);
            w2.y = eluf(acc[1][n][1] * inv2);
            w3.x = eluf(acc[1][n][2] * inv3);
            w3.y = eluf(acc[1][n][3] * inv3);
            *(float2*)(o0 + n * 8) = w0;
            *(float2*)(o1 + n * 8) = w1;
            *(float2*)(o2 + n * 8) = w2;
            *(float2*)(o3 + n * 8) = w3;
        }
    }
}

// ---------------------------------------------------------------------------
extern "C" void kernel_launch(void* const* d_in, const int* in_sizes, int n_in,
                              void* d_out, int out_size) {
    const float* h = (const float*)d_in[0];
    const float* W = (const float*)d_in[1];
    const float* a = (const float*)d_in[2];
    float* out = (float*)d_out;

    cudaFuncSetAttribute(k3_attn, cudaFuncAttributeMaxDynamicSharedMemorySize,
                         SMEM3_TOTAL);

    k1_proj<<<(BATCH * NTOK) / 64, 128>>>(h, W, a);
    k2_max<<<BATCH, 256>>>();
    dim3 g3(NTOK / 128, BATCH);
    k3_attn<<<g3, 512, SMEM3_TOTAL>>>(out);
}

// round 12
// speedup vs baseline: 2.2025x; 1.0567x over previous
#include <cuda_runtime.h>
#include <cuda_fp16.h>
#include <math.h>
#include <stdint.h>

#define BATCH 8
#define NTOK  2048
#define FDIM  64
#define ALPHA 0.2f

// ---------------- scratch (__device__ globals; no allocs allowed) ----------
__device__ __align__(16) __half g_WhT[BATCH * FDIM * NTOK];  // [b][o][j] fp16
__device__ float g_ssrc[BATCH * NTOK];
__device__ float g_sdst[BATCH * NTOK];
__device__ __align__(16) __half g_uh[BATCH * NTOK];          // e^(sd-M)   fp16
__device__ __align__(16) __half g_vh[BATCH * NTOK];          // e^(a(sd-M)) fp16
__device__ float g_maxs[BATCH];

__device__ __forceinline__ float eluf(float x) { return x > 0.f ? x : expm1f(x); }

__device__ __forceinline__ uint32_t smem_u32(const void* p) {
    uint32_t a;
    asm("{ .reg .u64 t; cvta.to.shared.u64 t, %1; cvt.u32.u64 %0, t; }" : "=r"(a) : "l"(p));
    return a;
}

__device__ __forceinline__ uint32_t h2u(__half2 h) {
    uint32_t r;
    asm("mov.b32 %0, %1;" : "=r"(r) : "r"(*(uint32_t*)&h));
    return r;
}

__device__ __forceinline__ void mma_f16(float* d, uint32_t a0, uint32_t a1,
                                        uint32_t a2, uint32_t a3,
                                        uint32_t b0, uint32_t b1) {
    asm volatile(
        "mma.sync.aligned.m16n8k16.row.col.f32.f16.f16.f32 "
        "{%0,%1,%2,%3}, {%4,%5,%6,%7}, {%8,%9}, {%0,%1,%2,%3};"
        : "+f"(d[0]), "+f"(d[1]), "+f"(d[2]), "+f"(d[3])
        : "r"(a0), "r"(a1), "r"(a2), "r"(a3), "r"(b0), "r"(b1));
}

__device__ __forceinline__ void ldm_x4(uint32_t* r, uint32_t addr) {
    asm volatile("ldmatrix.sync.aligned.m8n8.x4.shared.b16 {%0,%1,%2,%3}, [%4];"
                 : "=r"(r[0]), "=r"(r[1]), "=r"(r[2]), "=r"(r[3]) : "r"(addr));
}

// ---------------------------------------------------------------------------
// Kernel 1 (R10-validated): Wh via fp16 HMMA; exact fp32 scores s=h.(W@a).
// grid 256, 128 thr, 64 rows/CTA.
// ---------------------------------------------------------------------------
__global__ void __launch_bounds__(128) k1_proj(const float* __restrict__ h,
                                               const float* __restrict__ W,
                                               const float* __restrict__ a) {
    __shared__ float a_s[128];
    __shared__ float2 Wa_s[64];
    __shared__ __align__(16) __half WT_s[64 * 72];  // [o][k]
    __shared__ __align__(16) __half h_s[64 * 72];   // [j][k]
    __shared__ __align__(16) __half T_s[64 * 72];   // [o][j]

    int tid = threadIdx.x;
    int row0 = blockIdx.x * 64;
    int bb = row0 >> 11;
    int jbase = row0 & 2047;

    if (tid < 128) a_s[tid] = a[tid];
    __syncthreads();

    {
        int k = tid >> 1, oh = tid & 1;
        const float4* wr = (const float4*)(W + k * 64 + oh * 32);
        float pws = 0.f, pwd = 0.f;
#pragma unroll
        for (int f = 0; f < 8; f++) {
            float4 v = wr[f];
            int o = oh * 32 + f * 4;
            WT_s[(o + 0) * 72 + k] = __float2half(v.x);
            WT_s[(o + 1) * 72 + k] = __float2half(v.y);
            WT_s[(o + 2) * 72 + k] = __float2half(v.z);
            WT_s[(o + 3) * 72 + k] = __float2half(v.w);
            pws += v.x * a_s[o] + v.y * a_s[o + 1] + v.z * a_s[o + 2] + v.w * a_s[o + 3];
            pwd += v.x * a_s[64 + o] + v.y * a_s[65 + o] + v.z * a_s[66 + o] + v.w * a_s[67 + o];
        }
        pws += __shfl_xor_sync(0xffffffffu, pws, 1);
        pwd += __shfl_xor_sync(0xffffffffu, pwd, 1);
        if (oh == 0) Wa_s[k] = make_float2(pws, pwd);
    }

    int r = tid >> 1, hf = tid & 1;
    float4 hv[8];
    {
        const float4* hrow = (const float4*)(h + (size_t)(row0 + r) * 64 + hf * 32);
#pragma unroll
        for (int f = 0; f < 8; f++) hv[f] = hrow[f];
    }
    __syncthreads();

    {
        float ps = 0.f, pd = 0.f;
        __half2* hs2 = (__half2*)(h_s + r * 72 + hf * 32);
#pragma unroll
        for (int f = 0; f < 8; f++) {
            float4 v = hv[f];
            int k = hf * 32 + f * 4;
            float2 w0 = Wa_s[k], w1 = Wa_s[k + 1], w2 = Wa_s[k + 2], w3 = Wa_s[k + 3];
            ps += v.x * w0.x + v.y * w1.x + v.z * w2.x + v.w * w3.x;
            pd += v.x * w0.y + v.y * w1.y + v.z * w2.y + v.w * w3.y;
            hs2[f * 2]     = __floats2half2_rn(v.x, v.y);
            hs2[f * 2 + 1] = __floats2half2_rn(v.z, v.w);
        }
        ps += __shfl_xor_sync(0xffffffffu, ps, 1);
        pd += __shfl_xor_sync(0xffffffffu, pd, 1);
        if (hf == 0) {
            g_ssrc[row0 + r] = ps;
            g_sdst[row0 + r] = pd;
        }
    }
    __syncthreads();

    int w = tid >> 5, lane = tid & 31;
    uint32_t hs_b = smem_u32(h_s);
    uint32_t wt_b = smem_u32(WT_s);
    uint32_t aoff = ((w * 16 + ((lane >> 3) & 1) * 8 + (lane & 7)) * 36 +
                     ((lane >> 4) & 1) * 4) * 4;
    uint32_t boff = ((((lane >> 4) & 1) * 8 + (lane & 7)) * 36 +
                     ((lane >> 3) & 1) * 4) * 4;

    float acc[8][4];
#pragma unroll
    for (int n = 0; n < 8; n++)
#pragma unroll
        for (int i = 0; i < 4; i++) acc[n][i] = 0.f;

#pragma unroll
    for (int kk = 0; kk < 4; kk++) {
        uint32_t av[4];
        ldm_x4(av, hs_b + aoff + kk * 32);
#pragma unroll
        for (int nn = 0; nn < 4; nn++) {
            uint32_t bv[4];
            ldm_x4(bv, wt_b + boff + nn * 2304 + kk * 32);
            mma_f16(acc[2 * nn],     av[0], av[1], av[2], av[3], bv[0], bv[1]);
            mma_f16(acc[2 * nn + 1], av[0], av[1], av[2], av[3], bv[2], bv[3]);
        }
    }

    {
        int q = lane >> 2, c4 = lane & 3;
        int jr = w * 16 + q;
#pragma unroll
        for (int n = 0; n < 8; n++) {
            int o = n * 8 + 2 * c4;
            T_s[o * 72 + jr]           = __float2half(acc[n][0]);
            T_s[(o + 1) * 72 + jr]     = __float2half(acc[n][1]);
            T_s[o * 72 + jr + 8]       = __float2half(acc[n][2]);
            T_s[(o + 1) * 72 + jr + 8] = __float2half(acc[n][3]);
        }
    }
    __syncthreads();

    {
        const uint4* T4 = (const uint4*)T_s;
        uint4* dst = (uint4*)(g_WhT + (size_t)bb * FDIM * NTOK + jbase);
#pragma unroll
        for (int it = 0; it < 4; it++) {
            int idx = tid + it * 128;
            int o = idx >> 3, u4 = idx & 7;
            dst[o * 256 + u4] = T4[o * 9 + u4];
        }
    }
}

// ---------------------------------------------------------------------------
// Kernel 2: per-batch max of s_dst AND fp16 u~/v~ tables.  8 blocks.
//   u~ = e^(sd-M), v~ = e^(a(sd-M))  (both in (0,1] -> fp16-safe)
// ---------------------------------------------------------------------------
__global__ void __launch_bounds__(256) k2_prep() {
    __shared__ float red[8];
    __shared__ float sM;
    int b = blockIdx.x, tid = threadIdx.x;
    float m = -1e30f;
    for (int j = tid; j < NTOK; j += 256) m = fmaxf(m, g_sdst[b * NTOK + j]);
#pragma unroll
    for (int o = 16; o > 0; o >>= 1)
        m = fmaxf(m, __shfl_xor_sync(0xffffffffu, m, o));
    if ((tid & 31) == 0) red[tid >> 5] = m;
    __syncthreads();
    if (tid == 0) {
        float r = red[0];
#pragma unroll
        for (int i = 1; i < 8; i++) r = fmaxf(r, red[i]);
        sM = r;
        g_maxs[b] = r;
    }
    __syncthreads();
    float M = sM;
    for (int j = tid; j < NTOK; j += 256) {
        float d = g_sdst[b * NTOK + j] - M;
        g_uh[b * NTOK + j] = __float2half(expf(d));
        g_vh[b * NTOK + j] = __float2half(expf(ALPHA * d));
    }
}

// ---------------------------------------------------------------------------
// Kernel 3: fused attention, fp16x2 p-gen: p2 = hmax2(A2*u2, B2*v2).
//   128 CTAs (16 i-tiles x 8 b), 512 thr = 4 m-warps x 4 j-split,
//   2 m-tiles/warp; ldmatrix B; ones-col Z (constant B frag); dbl-buffered.
// ---------------------------------------------------------------------------
#define TBB      17408                    // 64 * 68 * 4 bytes per buffer
#define UOFF     (2 * TBB)
#define VOFF     (UOFF + 4096)
#define SMEM3_TOTAL (VOFF + 4096)

__global__ void __launch_bounds__(512, 1) k3_attn(float* __restrict__ out) {
    extern __shared__ char smem[];
    uint32_t sb = smem_u32(smem);
    const __half2* u2_s = (const __half2*)(smem + UOFF);
    const __half2* v2_s = (const __half2*)(smem + VOFF);

    int tid = threadIdx.x;
    int lane = tid & 31;
    int wid = tid >> 5;
    int mw = wid & 3, js = wid >> 2;
    int b = blockIdx.y;
    int i0 = blockIdx.x * 128;

    if (tid < 256) {
        const uint4* ug = (const uint4*)(g_uh + b * NTOK);
        const uint4* vg = (const uint4*)(g_vh + b * NTOK);
        ((uint4*)(smem + UOFF))[tid] = ug[tid];
        ((uint4*)(smem + VOFF))[tid] = vg[tid];
    }

    int q = lane >> 2, c4 = lane & 3;
    int rbase = i0 + mw * 32 + q;
    float M = g_maxs[b];
    __half2 A2[4], B2[4];
#pragma unroll
    for (int rr = 0; rr < 4; rr++) {
        float t = g_ssrc[b * NTOK + rbase + rr * 8] + M;
        float mi = t > 0.f ? t : ALPHA * t;
        A2[rr] = __float2half2_rn(expf(t - mi));
        B2[rr] = __float2half2_rn(expf(ALPHA * t - mi));
    }

    float acc[2][9][4];
#pragma unroll
    for (int mt = 0; mt < 2; mt++)
#pragma unroll
        for (int n = 0; n < 9; n++)
#pragma unroll
            for (int i = 0; i < 4; i++) acc[mt][n][i] = 0.f;

    uint32_t b_ones = (q == 0) ? 0x3C003C00u : 0u;
    uint32_t row_off = ((((lane >> 4) & 1) * 8 + (lane & 7)) * 68u) + ((lane >> 3) & 1) * 4u;

    const uint4* WhT4 = (const uint4*)(g_WhT + (size_t)b * FDIM * NTOK);
    int so = tid >> 4, sj = tid & 15;

    // stage tile 0
    {
        uint4* T0 = (uint4*)smem;
#pragma unroll
        for (int it = 0; it < 2; it++) {
            int o = so + it * 32;
            T0[o * 17 + sj] = WhT4[o * 256 + sj];
        }
    }
    __syncthreads();

    for (int t = 0; t < 16; t++) {
        uint32_t cur = sb + (t & 1) * TBB;
        uint4* nxt = (uint4*)(smem + ((t + 1) & 1) * TBB);
        uint4 pf[2];
        if (t < 15) {
#pragma unroll
            for (int it = 0; it < 2; it++)
                pf[it] = WhT4[(so + it * 32) * 256 + (t + 1) * 16 + sj];
        }

#pragma unroll
        for (int cc = 0; cc < 2; cc++) {
            int c = js * 2 + cc;
            int cb2 = t * 64 + c * 8;          // half2 index of chunk base
            __half2 ua = u2_s[cb2 + c4];
            __half2 ub = u2_s[cb2 + 4 + c4];
            __half2 va = v2_s[cb2 + c4];
            __half2 vb = v2_s[cb2 + 4 + c4];
            uint32_t af[2][4];
#pragma unroll
            for (int mt = 0; mt < 2; mt++) {
                int r0 = mt * 2, r1 = mt * 2 + 1;
                af[mt][0] = h2u(__hmax2(__hmul2(A2[r0], ua), __hmul2(B2[r0], va)));
                af[mt][1] = h2u(__hmax2(__hmul2(A2[r1], ua), __hmul2(B2[r1], va)));
                af[mt][2] = h2u(__hmax2(__hmul2(A2[r0], ub), __hmul2(B2[r0], vb)));
                af[mt][3] = h2u(__hmax2(__hmul2(A2[r1], ub), __hmul2(B2[r1], vb)));
            }
            uint32_t bf[4][4];
            uint32_t base = cur + (row_off + (uint32_t)c * 8) * 4;
#pragma unroll
            for (int nn = 0; nn < 4; nn++)
                ldm_x4(bf[nn], base + nn * 4352u);
#pragma unroll
            for (int n = 0; n < 8; n++) {
                uint32_t b0 = bf[n >> 1][(n & 1) * 2];
                uint32_t b1 = bf[n >> 1][(n & 1) * 2 + 1];
                mma_f16(acc[0][n], af[0][0], af[0][1], af[0][2], af[0][3], b0, b1);
                mma_f16(acc[1][n], af[1][0], af[1][1], af[1][2], af[1][3], b0, b1);
            }
            mma_f16(acc[0][8], af[0][0], af[0][1], af[0][2], af[0][3], b_ones, b_ones);
            mma_f16(acc[1][8], af[1][0], af[1][1], af[1][2], af[1][3], b_ones, b_ones);
        }

        if (t < 15) {
#pragma unroll
            for (int it = 0; it < 2; it++)
                nxt[(so + it * 32) * 17 + sj] = pf[it];
        }
        __syncthreads();
    }

    // ---- reduce across js groups (128 slots, stride 73, payload 72) ----
    float* red = (float*)smem;
    int slot = mw * 32 + lane;
    float* accf = &acc[0][0][0];
#pragma unroll
    for (int src = 1; src < 4; src++) {
        if (js == src) {
#pragma unroll
            for (int i = 0; i < 72; i++) red[slot * 73 + i] = accf[i];
        }
        __syncthreads();
        if (js == 0) {
#pragma unroll
            for (int i = 0; i < 72; i++) accf[i] += red[slot * 73 + i];
        }
        __syncthreads();
    }

    // ---- epilogue (js == 0) ----
    if (js == 0) {
        float z0 = __shfl_sync(0xffffffffu, acc[0][8][0], lane & 28);
        float z1 = __shfl_sync(0xffffffffu, acc[0][8][2], lane & 28);
        float z2 = __shfl_sync(0xffffffffu, acc[1][8][0], lane & 28);
        float z3 = __shfl_sync(0xffffffffu, acc[1][8][2], lane & 28);
        float inv0 = 1.f / z0, inv1 = 1.f / z1;
        float inv2 = 1.f / z2, inv3 = 1.f / z3;

        float* o0 = out + ((size_t)(b * NTOK + rbase)) * 64 + 2 * c4;
        float* o1 = o0 + 8 * 64;
        float* o2 = o0 + 16 * 64;
        float* o3 = o0 + 24 * 64;
#pragma unroll
        for (int n = 0; n < 8; n++) {
            float2 w0, w1, w2, w3;
            w0.x = eluf(acc[0][n][0] * inv0);
            w0.y = eluf(acc[0][n][1] * inv0);
            w1.x = eluf(acc[0][n][2] * inv1);
            w1.y = eluf(acc[0][n][3] * inv1);
            w2.x = eluf(acc[1][n][0] * inv2);
            w2.y = eluf(acc[1][n][1] * inv2);
            w3.x = eluf(acc[1][n][2] * inv3);
            w3.y = eluf(acc[1][n][3] * inv3);
            *(float2*)(o0 + n * 8) = w0;
            *(float2*)(o1 + n * 8) = w1;
            *(float2*)(o2 + n * 8) = w2;
            *(float2*)(o3 + n * 8) = w3;
        }
    }
}

// ---------------------------------------------------------------------------
extern "C" void kernel_launch(void* const* d_in, const int* in_sizes, int n_in,
                              void* d_out, int out_size) {
    const float* h = (const float*)d_in[0];
    const float* W = (const float*)d_in[1];
    const float* a = (const float*)d_in[2];
    float* out = (float*)d_out;

    cudaFuncSetAttribute(k3_attn, cudaFuncAttributeMaxDynamicSharedMemorySize,
                         SMEM3_TOTAL);

    k1_proj<<<(BATCH * NTOK) / 64, 128>>>(h, W, a);
    k2_prep<<<BATCH, 256>>>();
    dim3 g3(NTOK / 128, BATCH);
    k3_attn<<<g3, 512, SMEM3_TOTAL>>>(out);
}

// round 13
// speedup vs baseline: 2.2225x; 1.0091x over previous
#include <cuda_runtime.h>
#include <cuda_fp16.h>
#include <math.h>
#include <stdint.h>

#define BATCH 8
#define NTOK  2048
#define FDIM  64
#define ALPHA 0.2f

// ---------------- scratch (__device__ globals; no allocs allowed) ----------
__device__ __align__(16) __half g_WhT[BATCH * FDIM * NTOK];  // [b][o][j] fp16
__device__ float g_ssrc[BATCH * NTOK];
__device__ float g_sdst[BATCH * NTOK];
__device__ __align__(16) __half g_uh[BATCH * NTOK];          // e^(sd-M)   fp16
__device__ __align__(16) __half g_vh[BATCH * NTOK];          // e^(a(sd-M)) fp16
__device__ float g_maxs[BATCH];

__device__ __forceinline__ float eluf(float x) { return x > 0.f ? x : expm1f(x); }

__device__ __forceinline__ uint32_t smem_u32(const void* p) {
    uint32_t a;
    asm("{ .reg .u64 t; cvta.to.shared.u64 t, %1; cvt.u32.u64 %0, t; }" : "=r"(a) : "l"(p));
    return a;
}

__device__ __forceinline__ uint32_t h2u(__half2 h) {
    uint32_t r;
    asm("mov.b32 %0, %1;" : "=r"(r) : "r"(*(uint32_t*)&h));
    return r;
}

__device__ __forceinline__ void cp16(uint32_t dst, const void* src) {
    asm volatile("cp.async.cg.shared.global [%0], [%1], 16;" :: "r"(dst), "l"(src));
}
#define CP_COMMIT() asm volatile("cp.async.commit_group;" ::: "memory")
#define CP_WAIT0()  asm volatile("cp.async.wait_group 0;" ::: "memory")

__device__ __forceinline__ void mma_f16(float* d, uint32_t a0, uint32_t a1,
                                        uint32_t a2, uint32_t a3,
                                        uint32_t b0, uint32_t b1) {
    asm volatile(
        "mma.sync.aligned.m16n8k16.row.col.f32.f16.f16.f32 "
        "{%0,%1,%2,%3}, {%4,%5,%6,%7}, {%8,%9}, {%0,%1,%2,%3};"
        : "+f"(d[0]), "+f"(d[1]), "+f"(d[2]), "+f"(d[3])
        : "r"(a0), "r"(a1), "r"(a2), "r"(a3), "r"(b0), "r"(b1));
}

__device__ __forceinline__ void ldm_x4(uint32_t* r, uint32_t addr) {
    asm volatile("ldmatrix.sync.aligned.m8n8.x4.shared.b16 {%0,%1,%2,%3}, [%4];"
                 : "=r"(r[0]), "=r"(r[1]), "=r"(r[2]), "=r"(r[3]) : "r"(addr));
}

// ---------------------------------------------------------------------------
// Kernel 1 (R10-validated, 7.9us): Wh via fp16 HMMA; exact fp32 scores.
// ---------------------------------------------------------------------------
__global__ void __launch_bounds__(128) k1_proj(const float* __restrict__ h,
                                               const float* __restrict__ W,
                                               const float* __restrict__ a) {
    __shared__ float a_s[128];
    __shared__ float2 Wa_s[64];
    __shared__ __align__(16) __half WT_s[64 * 72];  // [o][k]
    __shared__ __align__(16) __half h_s[64 * 72];   // [j][k]
    __shared__ __align__(16) __half T_s[64 * 72];   // [o][j]

    int tid = threadIdx.x;
    int row0 = blockIdx.x * 64;
    int bb = row0 >> 11;
    int jbase = row0 & 2047;

    if (tid < 128) a_s[tid] = a[tid];
    __syncthreads();

    {
        int k = tid >> 1, oh = tid & 1;
        const float4* wr = (const float4*)(W + k * 64 + oh * 32);
        float pws = 0.f, pwd = 0.f;
#pragma unroll
        for (int f = 0; f < 8; f++) {
            float4 v = wr[f];
            int o = oh * 32 + f * 4;
            WT_s[(o + 0) * 72 + k] = __float2half(v.x);
            WT_s[(o + 1) * 72 + k] = __float2half(v.y);
            WT_s[(o + 2) * 72 + k] = __float2half(v.z);
            WT_s[(o + 3) * 72 + k] = __float2half(v.w);
            pws += v.x * a_s[o] + v.y * a_s[o + 1] + v.z * a_s[o + 2] + v.w * a_s[o + 3];
            pwd += v.x * a_s[64 + o] + v.y * a_s[65 + o] + v.z * a_s[66 + o] + v.w * a_s[67 + o];
        }
        pws += __shfl_xor_sync(0xffffffffu, pws, 1);
        pwd += __shfl_xor_sync(0xffffffffu, pwd, 1);
        if (oh == 0) Wa_s[k] = make_float2(pws, pwd);
    }

    int r = tid >> 1, hf = tid & 1;
    float4 hv[8];
    {
        const float4* hrow = (const float4*)(h + (size_t)(row0 + r) * 64 + hf * 32);
#pragma unroll
        for (int f = 0; f < 8; f++) hv[f] = hrow[f];
    }
    __syncthreads();

    {
        float ps = 0.f, pd = 0.f;
        __half2* hs2 = (__half2*)(h_s + r * 72 + hf * 32);
#pragma unroll
        for (int f = 0; f < 8; f++) {
            float4 v = hv[f];
            int k = hf * 32 + f * 4;
            float2 w0 = Wa_s[k], w1 = Wa_s[k + 1], w2 = Wa_s[k + 2], w3 = Wa_s[k + 3];
            ps += v.x * w0.x + v.y * w1.x + v.z * w2.x + v.w * w3.x;
            pd += v.x * w0.y + v.y * w1.y + v.z * w2.y + v.w * w3.y;
            hs2[f * 2]     = __floats2half2_rn(v.x, v.y);
            hs2[f * 2 + 1] = __floats2half2_rn(v.z, v.w);
        }
        ps += __shfl_xor_sync(0xffffffffu, ps, 1);
        pd += __shfl_xor_sync(0xffffffffu, pd, 1);
        if (hf == 0) {
            g_ssrc[row0 + r] = ps;
            g_sdst[row0 + r] = pd;
        }
    }
    __syncthreads();

    int w = tid >> 5, lane = tid & 31;
    uint32_t hs_b = smem_u32(h_s);
    uint32_t wt_b = smem_u32(WT_s);
    uint32_t aoff = ((w * 16 + ((lane >> 3) & 1) * 8 + (lane & 7)) * 36 +
                     ((lane >> 4) & 1) * 4) * 4;
    uint32_t boff = ((((lane >> 4) & 1) * 8 + (lane & 7)) * 36 +
                     ((lane >> 3) & 1) * 4) * 4;

    float acc[8][4];
#pragma unroll
    for (int n = 0; n < 8; n++)
#pragma unroll
        for (int i = 0; i < 4; i++) acc[n][i] = 0.f;

#pragma unroll
    for (int kk = 0; kk < 4; kk++) {
        uint32_t av[4];
        ldm_x4(av, hs_b + aoff + kk * 32);
#pragma unroll
        for (int nn = 0; nn < 4; nn++) {
            uint32_t bv[4];
            ldm_x4(bv, wt_b + boff + nn * 2304 + kk * 32);
            mma_f16(acc[2 * nn],     av[0], av[1], av[2], av[3], bv[0], bv[1]);
            mma_f16(acc[2 * nn + 1], av[0], av[1], av[2], av[3], bv[2], bv[3]);
        }
    }

    {
        int q = lane >> 2, c4 = lane & 3;
        int jr = w * 16 + q;
#pragma unroll
        for (int n = 0; n < 8; n++) {
            int o = n * 8 + 2 * c4;
            T_s[o * 72 + jr]           = __float2half(acc[n][0]);
            T_s[(o + 1) * 72 + jr]     = __float2half(acc[n][1]);
            T_s[o * 72 + jr + 8]       = __float2half(acc[n][2]);
            T_s[(o + 1) * 72 + jr + 8] = __float2half(acc[n][3]);
        }
    }
    __syncthreads();

    {
        const uint4* T4 = (const uint4*)T_s;
        uint4* dst = (uint4*)(g_WhT + (size_t)bb * FDIM * NTOK + jbase);
#pragma unroll
        for (int it = 0; it < 4; it++) {
            int idx = tid + it * 128;
            int o = idx >> 3, u4 = idx & 7;
            dst[o * 256 + u4] = T4[o * 9 + u4];
        }
    }
}

// ---------------------------------------------------------------------------
// Kernel 2: per-batch max of s_dst AND fp16 u~/v~ tables.
// ---------------------------------------------------------------------------
__global__ void __launch_bounds__(256) k2_prep() {
    __shared__ float red[8];
    __shared__ float sM;
    int b = blockIdx.x, tid = threadIdx.x;
    float m = -1e30f;
    for (int j = tid; j < NTOK; j += 256) m = fmaxf(m, g_sdst[b * NTOK + j]);
#pragma unroll
    for (int o = 16; o > 0; o >>= 1)
        m = fmaxf(m, __shfl_xor_sync(0xffffffffu, m, o));
    if ((tid & 31) == 0) red[tid >> 5] = m;
    __syncthreads();
    if (tid == 0) {
        float r = red[0];
#pragma unroll
        for (int i = 1; i < 8; i++) r = fmaxf(r, red[i]);
        sM = r;
        g_maxs[b] = r;
    }
    __syncthreads();
    float M = sM;
    for (int j = tid; j < NTOK; j += 256) {
        float d = g_sdst[b * NTOK + j] - M;
        g_uh[b * NTOK + j] = __float2half(expf(d));
        g_vh[b * NTOK + j] = __float2half(expf(ALPHA * d));
    }
}

// ---------------------------------------------------------------------------
// Kernel 3: fused attention.  256-j tiles (8), cp.async staging, ONE
// __syncthreads per tile.  fp16x2 p-gen, ldmatrix B, ones-col Z.
//   128 CTAs, 512 thr = 4 m-warps x 4 j-split; B row stride 132 words.
// ---------------------------------------------------------------------------
#define STRIDE_W  132                      // words per o-row (256 halfs + pad)
#define TBB       (64 * STRIDE_W * 4)      // 33792 B per buffer
#define UOFF      (2 * TBB)
#define VOFF      (UOFF + 4096)
#define SMEM3_TOTAL (VOFF + 4096)

__global__ void __launch_bounds__(512, 1) k3_attn(float* __restrict__ out) {
    extern __shared__ char smem[];
    uint32_t sb = smem_u32(smem);
    const __half2* u2_s = (const __half2*)(smem + UOFF);
    const __half2* v2_s = (const __half2*)(smem + VOFF);

    int tid = threadIdx.x;
    int lane = tid & 31;
    int wid = tid >> 5;
    int mw = wid & 3, js = wid >> 2;
    int b = blockIdx.y;
    int i0 = blockIdx.x * 128;

    if (tid < 256) {
        const uint4* ug = (const uint4*)(g_uh + b * NTOK);
        const uint4* vg = (const uint4*)(g_vh + b * NTOK);
        ((uint4*)(smem + UOFF))[tid] = ug[tid];
        ((uint4*)(smem + VOFF))[tid] = vg[tid];
    }

    int q = lane >> 2, c4 = lane & 3;
    int rbase = i0 + mw * 32 + q;
    float M = g_maxs[b];
    __half2 A2[4], B2[4];
#pragma unroll
    for (int rr = 0; rr < 4; rr++) {
        float t = g_ssrc[b * NTOK + rbase + rr * 8] + M;
        float mi = t > 0.f ? t : ALPHA * t;
        A2[rr] = __float2half2_rn(expf(t - mi));
        B2[rr] = __float2half2_rn(expf(ALPHA * t - mi));
    }

    float acc[2][9][4];
#pragma unroll
    for (int mt = 0; mt < 2; mt++)
#pragma unroll
        for (int n = 0; n < 9; n++)
#pragma unroll
            for (int i = 0; i < 4; i++) acc[mt][n][i] = 0.f;

    uint32_t b_ones = (q == 0) ? 0x3C003C00u : 0u;
    uint32_t row_off = ((((lane >> 4) & 1) * 8 + (lane & 7)) * (uint32_t)STRIDE_W) +
                       ((lane >> 3) & 1) * 4u;

    const uint4* WhT4 = (const uint4*)(g_WhT + (size_t)b * FDIM * NTOK);
    int so = tid >> 5, su = tid & 31;      // staging: o-row (it adds 16), uint4 col

    // prologue: issue tile 0 via cp.async
#pragma unroll
    for (int it = 0; it < 4; it++) {
        int o = so + it * 16;
        cp16(sb + (uint32_t)(o * STRIDE_W + su * 4) * 4,
             WhT4 + o * 256 + su);
    }
    CP_COMMIT();

    for (int t = 0; t < 8; t++) {
        CP_WAIT0();
        __syncthreads();                    // tile t ready; buf t^1 free

        if (t < 7) {
            uint32_t nb = sb + ((t + 1) & 1) * (uint32_t)TBB;
#pragma unroll
            for (int it = 0; it < 4; it++) {
                int o = so + it * 16;
                cp16(nb + (uint32_t)(o * STRIDE_W + su * 4) * 4,
                     WhT4 + o * 256 + (t + 1) * 32 + su);
            }
            CP_COMMIT();
        }

        uint32_t cur = sb + (t & 1) * (uint32_t)TBB;
#pragma unroll
        for (int cc = 0; cc < 4; cc++) {
            int c = js * 4 + cc;            // chunk 0..15 within 256-j tile
            int cb2 = t * 128 + c * 8;      // half2 index of chunk base
            __half2 ua = u2_s[cb2 + c4];
            __half2 ub = u2_s[cb2 + 4 + c4];
            __half2 va = v2_s[cb2 + c4];
            __half2 vb = v2_s[cb2 + 4 + c4];
            uint32_t af[2][4];
#pragma unroll
            for (int mt = 0; mt < 2; mt++) {
                int r0 = mt * 2, r1 = mt * 2 + 1;
                af[mt][0] = h2u(__hmax2(__hmul2(A2[r0], ua), __hmul2(B2[r0], va)));
                af[mt][1] = h2u(__hmax2(__hmul2(A2[r1], ua), __hmul2(B2[r1], va)));
                af[mt][2] = h2u(__hmax2(__hmul2(A2[r0], ub), __hmul2(B2[r0], vb)));
                af[mt][3] = h2u(__hmax2(__hmul2(A2[r1], ub), __hmul2(B2[r1], vb)));
            }
            uint32_t bf[4][4];
            uint32_t base = cur + (row_off + (uint32_t)c * 8) * 4;
#pragma unroll
            for (int nn = 0; nn < 4; nn++)
                ldm_x4(bf[nn], base + (uint32_t)nn * (16u * STRIDE_W * 4u));
#pragma unroll
            for (int n = 0; n < 8; n++) {
                uint32_t b0 = bf[n >> 1][(n & 1) * 2];
                uint32_t b1 = bf[n >> 1][(n & 1) * 2 + 1];
                mma_f16(acc[0][n], af[0][0], af[0][1], af[0][2], af[0][3], b0, b1);
                mma_f16(acc[1][n], af[1][0], af[1][1], af[1][2], af[1][3], b0, b1);
            }
            mma_f16(acc[0][8], af[0][0], af[0][1], af[0][2], af[0][3], b_ones, b_ones);
            mma_f16(acc[1][8], af[1][0], af[1][1], af[1][2], af[1][3], b_ones, b_ones);
        }
    }
    __syncthreads();                        // done reading buffers

    // ---- reduce across js groups (128 slots, stride 73, payload 72) ----
    float* red = (float*)smem;
    int slot = mw * 32 + lane;
    float* accf = &acc[0][0][0];
#pragma unroll
    for (int src = 1; src < 4; src++) {
        if (js == src) {
#pragma unroll
            for (int i = 0; i < 72; i++) red[slot * 73 + i] = accf[i];
        }
        __syncthreads();
        if (js == 0) {
#pragma unroll
            for (int i = 0; i < 72; i++) accf[i] += red[slot * 73 + i];
        }
        __syncthreads();
    }

    // ---- epilogue (js == 0) ----
    if (js == 0) {
        float z0 = __shfl_sync(0xffffffffu, acc[0][8][0], lane & 28);
        float z1 = __shfl_sync(0xffffffffu, acc[0][8][2], lane & 28);
        float z2 = __shfl_sync(0xffffffffu, acc[1][8][0], lane & 28);
        float z3 = __shfl_sync(0xffffffffu, acc[1][8][2], lane & 28);
        float inv0 = 1.f / z0, inv1 = 1.f / z1;
        float inv2 = 1.f / z2, inv3 = 1.f / z3;

        float* o0 = out + ((size_t)(b * NTOK + rbase)) * 64 + 2 * c4;
        float* o1 = o0 + 8 * 64;
        float* o2 = o0 + 16 * 64;
        float* o3 = o0 + 24 * 64;
#pragma unroll
        for (int n = 0; n < 8; n++) {
            float2 w0, w1, w2, w3;
            w0.x = eluf(acc[0][n][0] * inv0);
            w0.y = eluf(acc[0][n][1] * inv0);
            w1.x = eluf(acc[0][n][2] * inv1);
            w1.y = eluf(acc[0][n][3] * inv1);
            w2.x = eluf(acc[1][n][0] * inv2);
            w2.y = eluf(acc[1][n][1] * inv2);
            w3.x = eluf(acc[1][n][2] * inv3);
            w3.y = eluf(acc[1][n][3] * inv3);
            *(float2*)(o0 + n * 8) = w0;
            *(float2*)(o1 + n * 8) = w1;
            *(float2*)(o2 + n * 8) = w2;
            *(float2*)(o3 + n * 8) = w3;
        }
    }
}

// ---------------------------------------------------------------------------
extern "C" void kernel_launch(void* const* d_in, const int* in_sizes, int n_in,
                              void* d_out, int out_size) {
    const float* h = (const float*)d_in[0];
    const float* W = (const float*)d_in[1];
    const float* a = (const float*)d_in[2];
    float* out = (float*)d_out;

    cudaFuncSetAttribute(k3_attn, cudaFuncAttributeMaxDynamicSharedMemorySize,
                         SMEM3_TOTAL);

    k1_proj<<<(BATCH * NTOK) / 64, 128>>>(h, W, a);
    k2_prep<<<BATCH, 256>>>();
    dim3 g3(NTOK / 128, BATCH);
    k3_attn<<<g3, 512, SMEM3_TOTAL>>>(out);
}